// round 5
// baseline (speedup 1.0000x reference)
#include <cuda_runtime.h>
#include <cuda_bf16.h>
#include <math.h>
#include <stdint.h>

#define BATCH 8
#define SEQ   2048
#define NBL   (BATCH*SEQ)          // 16384
#define DM    512
#define DIN   1024
#define NH    16
#define HD    64
#define DS    64
#define CONVD 1152
#define DPROJ 2192
#define DFF   2048
#define EPSR  1e-6f

// ===================== scratch (static device; no cudaMalloc) =====================
static __device__ float g_xraw[(size_t)NBL*CONVD];  // in-proj xBC (pre-conv), compact
static __device__ float g_xbc[(size_t)NBL*CONVD];   // conv+silu output
static __device__ float g_yf[(size_t)NBL*DIN];      // forward scan out (+D*x)
static __device__ float g_yb[(size_t)NBL*DIN];      // backward scan out
// split-bf16 activations
static __device__ __nv_bfloat16 g_uh[(size_t)NBL*DM],  g_ul[(size_t)NBL*DM];
static __device__ __nv_bfloat16 g_y2h[(size_t)NBL*DIN], g_y2l[(size_t)NBL*DIN];
static __device__ __nv_bfloat16 g_hh[(size_t)NBL*DM],  g_hl[(size_t)NBL*DM];
static __device__ __nv_bfloat16 g_ffh[(size_t)NBL*DFF], g_ffl[(size_t)NBL*DFF];
// split-bf16 transposed weights [N,K]
static __device__ __nv_bfloat16 g_wih[(size_t)DPROJ*DM], g_wil[(size_t)DPROJ*DM];
static __device__ __nv_bfloat16 g_woh[(size_t)DM*DIN],   g_wol[(size_t)DM*DIN];
static __device__ __nv_bfloat16 g_w1h[(size_t)DFF*DM],   g_w1l[(size_t)DFF*DM];
static __device__ __nv_bfloat16 g_w2h[(size_t)DM*DFF],   g_w2l[(size_t)DM*DFF];

typedef unsigned long long ull;

// ===================== helpers =====================
__device__ __forceinline__ uint32_t smem_to_u32(const void* smem_ptr) {
    uint32_t addr;
    asm("{ .reg .u64 tmp; cvta.to.shared.u64 tmp, %1; cvt.u32.u64 %0, tmp; }"
        : "=r"(addr) : "l"(smem_ptr));
    return addr;
}
__device__ __forceinline__ void cp_async16(uint32_t dst, const void* src, uint32_t bytes){
    asm volatile("cp.async.cg.shared.global [%0], [%1], 16, %2;"
                 :: "r"(dst), "l"(src), "r"(bytes));
}
#define CP_COMMIT() asm volatile("cp.async.commit_group;")
#define CP_WAIT1()  asm volatile("cp.async.wait_group 1;")
#define CP_WAIT0()  asm volatile("cp.async.wait_group 0;")

__device__ __forceinline__ void ldm_x4(uint32_t addr, uint32_t& r0, uint32_t& r1,
                                       uint32_t& r2, uint32_t& r3){
    asm volatile("ldmatrix.sync.aligned.m8n8.x4.shared.b16 {%0,%1,%2,%3}, [%4];"
                 : "=r"(r0), "=r"(r1), "=r"(r2), "=r"(r3) : "r"(addr));
}
__device__ __forceinline__ void mma16816(float* c, const uint32_t* a, const uint32_t* b){
    asm volatile(
        "mma.sync.aligned.m16n8k16.row.col.f32.bf16.bf16.f32 "
        "{%0,%1,%2,%3}, {%4,%5,%6,%7}, {%8,%9}, {%0,%1,%2,%3};"
        : "+f"(c[0]), "+f"(c[1]), "+f"(c[2]), "+f"(c[3])
        : "r"(a[0]), "r"(a[1]), "r"(a[2]), "r"(a[3]), "r"(b[0]), "r"(b[1]));
}

// packed f32x2 (Blackwell)
__device__ __forceinline__ ull pack2(float lo, float hi){
    ull r; asm("mov.b64 %0, {%1,%2};" : "=l"(r) : "f"(lo), "f"(hi)); return r;
}
__device__ __forceinline__ void unpack2(ull v, float& lo, float& hi){
    asm("mov.b64 {%0,%1}, %2;" : "=f"(lo), "=f"(hi) : "l"(v));
}
__device__ __forceinline__ ull fma2(ull a, ull b, ull c){
    ull d; asm("fma.rn.f32x2 %0, %1, %2, %3;" : "=l"(d) : "l"(a), "l"(b), "l"(c)); return d;
}
__device__ __forceinline__ ull mul2(ull a, ull b){
    ull d; asm("mul.rn.f32x2 %0, %1, %2;" : "=l"(d) : "l"(a), "l"(b)); return d;
}
__device__ __forceinline__ ull add2(ull a, ull b){
    ull d; asm("add.rn.f32x2 %0, %1, %2;" : "=l"(d) : "l"(a), "l"(b)); return d;
}

__device__ __forceinline__ float siluf(float x){ return x / (1.f + expf(-x)); }
__device__ __forceinline__ float geluf(float x){
    float x3 = x*x*x;
    return 0.5f*x*(1.f + tanhf(0.7978845608028654f*(x + 0.044715f*x3)));
}
__device__ __forceinline__ float softplusf(float x){
    return fmaxf(x, 0.f) + log1pf(expf(-fabsf(x)));
}
__device__ __forceinline__ void split_bf16(float v, __nv_bfloat16& h, __nv_bfloat16& l){
    h = __float2bfloat16(v);
    l = __float2bfloat16(v - __bfloat162float(h));
}

// ===================== weight transpose + split: W[K,N] -> T_hi/lo[N,K] ==========
__global__ void wconv_kernel(const float* __restrict__ W,
                             __nv_bfloat16* __restrict__ Th, __nv_bfloat16* __restrict__ Tl,
                             int K, int N){
    __shared__ float tile[32][33];
    int n0 = blockIdx.x*32, k0 = blockIdx.y*32;
    int tx = threadIdx.x, ty = threadIdx.y;   // 32 x 8
    #pragma unroll
    for (int i=0;i<32;i+=8){
        int k = k0+ty+i, n = n0+tx;
        tile[ty+i][tx] = (n < N) ? W[(size_t)k*N + n] : 0.f;
    }
    __syncthreads();
    #pragma unroll
    for (int i=0;i<32;i+=8){
        int n = n0+ty+i, k = k0+tx;
        if (n < N){
            float v = tile[tx][ty+i];
            __nv_bfloat16 h, l; split_bf16(v, h, l);
            Th[(size_t)n*K + k] = h;
            Tl[(size_t)n*K + k] = l;
        }
    }
}

// ===================== split-bf16 HMMA GEMM (unchanged from round 4) =============
#define BK 32
#define LDSB 80
#define MAT_ELEMS (128*40)
#define STAGE_ELEMS (4*MAT_ELEMS)
#define STAGE_BYTES (STAGE_ELEMS*2)
#define GSMEM_BYTES (3*STAGE_BYTES)

template<int MODE>
__global__ void __launch_bounds__(256,1)
mma_gemm(const __nv_bfloat16* __restrict__ Ah, const __nv_bfloat16* __restrict__ Al,
         const __nv_bfloat16* __restrict__ Bh, const __nv_bfloat16* __restrict__ Bl,
         int N, int K,
         float* __restrict__ C, const float* __restrict__ bias,
         const float* __restrict__ res,
         __nv_bfloat16* __restrict__ Oh, __nv_bfloat16* __restrict__ Ol,
         float* __restrict__ z_out, float* __restrict__ xraw,
         float* __restrict__ dt_out, const float* __restrict__ dtb)
{
    extern __shared__ __nv_bfloat16 smem[];
    const uint32_t sb = smem_to_u32(smem);
    const int tid = threadIdx.x;
    const int lane = tid & 31, wid = tid >> 5;
    const int row0 = blockIdx.y * 128;
    const int n0   = blockIdx.x * 128;
    const int wm0 = (wid & 3) * 32;
    const int wn0 = (wid >> 2) * 64;

    const int r_a  = tid >> 2, c8 = (tid & 3) * 8;
    const uint32_t aoff = (uint32_t)((lane & 15) * LDSB + (lane >> 4) * 16);
    const uint32_t boff = (uint32_t)(((lane & 7) + ((lane & 16) >> 1)) * LDSB + (lane & 8) * 2);

    float acc[2][8][4];
    #pragma unroll
    for (int i=0;i<2;i++)
        #pragma unroll
        for (int j=0;j<8;j++)
            #pragma unroll
            for (int q=0;q<4;q++) acc[i][j][q]=0.f;

    const int nch = K / BK;

    auto issue = [&](int ch){
        const int k0 = ch * BK;
        uint32_t base = sb + (uint32_t)((ch % 3) * STAGE_BYTES);
        #pragma unroll
        for (int i=0;i<2;i++){
            int r = r_a + i*64;
            size_t g = (size_t)(row0 + r) * K + k0 + c8;
            uint32_t so = (uint32_t)(r * LDSB + c8 * 2);
            cp_async16(base + so,                         Ah + g, 16);
            cp_async16(base + (uint32_t)MAT_ELEMS*2 + so, Al + g, 16);
        }
        #pragma unroll
        for (int i=0;i<2;i++){
            int r = r_a + i*64;
            int n = n0 + r;
            int valid = (n < N);
            size_t g = (size_t)(valid ? n : 0) * K + k0 + c8;
            uint32_t so = (uint32_t)(r * LDSB + c8 * 2);
            uint32_t bytes = valid ? 16u : 0u;
            cp_async16(base + (uint32_t)(2*MAT_ELEMS)*2 + so, Bh + g, bytes);
            cp_async16(base + (uint32_t)(3*MAT_ELEMS)*2 + so, Bl + g, bytes);
        }
        CP_COMMIT();
    };

    issue(0); issue(1);
    for (int ch = 0; ch < nch; ch++){
        if (ch + 1 < nch) CP_WAIT1(); else CP_WAIT0();
        __syncthreads();
        if (ch + 2 < nch) issue(ch + 2);

        const uint32_t base = sb + (uint32_t)((ch % 3) * STAGE_BYTES);
        const uint32_t bAh = base;
        const uint32_t bAl = base + (uint32_t)MAT_ELEMS*2;
        const uint32_t bBh = base + (uint32_t)(2*MAT_ELEMS)*2;
        const uint32_t bBl = base + (uint32_t)(3*MAT_ELEMS)*2;

        #pragma unroll
        for (int ks = 0; ks < BK; ks += 16){
            uint32_t ah[2][4], al[2][4], bh[8][2], bl[8][2];
            #pragma unroll
            for (int mt = 0; mt < 2; mt++){
                uint32_t ao = (uint32_t)((wm0 + mt*16) * LDSB + ks*2) + aoff;
                ldm_x4(bAh + ao, ah[mt][0], ah[mt][1], ah[mt][2], ah[mt][3]);
                ldm_x4(bAl + ao, al[mt][0], al[mt][1], al[mt][2], al[mt][3]);
            }
            #pragma unroll
            for (int p = 0; p < 4; p++){
                uint32_t bo = (uint32_t)((wn0 + p*16) * LDSB + ks*2) + boff;
                ldm_x4(bBh + bo, bh[2*p][0], bh[2*p][1], bh[2*p+1][0], bh[2*p+1][1]);
                ldm_x4(bBl + bo, bl[2*p][0], bl[2*p][1], bl[2*p+1][0], bl[2*p+1][1]);
            }
            #pragma unroll
            for (int mt = 0; mt < 2; mt++)
                #pragma unroll
                for (int nt = 0; nt < 8; nt++)
                    mma16816(acc[mt][nt], ah[mt], bh[nt]);
            #pragma unroll
            for (int mt = 0; mt < 2; mt++)
                #pragma unroll
                for (int nt = 0; nt < 8; nt++)
                    mma16816(acc[mt][nt], ah[mt], bl[nt]);
            #pragma unroll
            for (int mt = 0; mt < 2; mt++)
                #pragma unroll
                for (int nt = 0; nt < 8; nt++)
                    mma16816(acc[mt][nt], al[mt], bh[nt]);
        }
        __syncthreads();
    }

    const int rb = row0 + wm0 + (lane >> 2);
    const int cb = n0 + wn0 + (lane & 3) * 2;
    #pragma unroll
    for (int mt = 0; mt < 2; mt++){
        #pragma unroll
        for (int nt = 0; nt < 8; nt++){
            int c = cb + nt*8;
            if (c >= N) continue;
            #pragma unroll
            for (int half = 0; half < 2; half++){
                int r = rb + mt*16 + half*8;
                float v0 = acc[mt][nt][half*2+0];
                float v1 = acc[mt][nt][half*2+1];
                size_t o = (size_t)r*N + c;
                if (MODE == 0){
                    *(float2*)(C + o) = make_float2(v0, v1);
                } else if (MODE == 1){
                    v0 = geluf(v0 + bias[c]);
                    v1 = geluf(v1 + bias[c+1]);
                    __nv_bfloat16 h0,l0,h1,l1;
                    split_bf16(v0,h0,l0); split_bf16(v1,h1,l1);
                    __nv_bfloat162 ph2; ph2.x=h0; ph2.y=h1;
                    __nv_bfloat162 pl2; pl2.x=l0; pl2.y=l1;
                    *(__nv_bfloat162*)(Oh + o) = ph2;
                    *(__nv_bfloat162*)(Ol + o) = pl2;
                } else if (MODE == 2){
                    float2 rv = *(const float2*)(res + o);
                    *(float2*)(C + o) = make_float2(v0 + bias[c]   + 2.f*rv.x,
                                                    v1 + bias[c+1] + 2.f*rv.y);
                } else {
                    if (c < DIN){
                        *(float2*)(z_out + (size_t)r*DIN + c) = make_float2(v0, v1);
                    } else if (c < DIN + CONVD){
                        *(float2*)(xraw + (size_t)r*CONVD + (c - DIN)) = make_float2(v0, v1);
                    } else {
                        int hh2 = c - (DIN + CONVD);
                        dt_out[(size_t)r*NH + hh2]     = softplusf(v0 + dtb[hh2]);
                        dt_out[(size_t)r*NH + hh2 + 1] = softplusf(v1 + dtb[hh2+1]);
                    }
                }
            }
        }
    }
}

// ===================== u = rmsnorm(x*mask) -> bf16 hi/lo =====================
__global__ void __launch_bounds__(128) prenorm_kernel(const float* __restrict__ x,
                                                      const float* __restrict__ mask,
                                                      __nv_bfloat16* __restrict__ uh,
                                                      __nv_bfloat16* __restrict__ ul){
    int row = blockIdx.x; int t = threadIdx.x;
    float mk = mask[row];
    float4 a = ((const float4*)(x + (size_t)row*DM))[t];
    a.x*=mk; a.y*=mk; a.z*=mk; a.w*=mk;
    float ss = a.x*a.x + a.y*a.y + a.z*a.z + a.w*a.w;
    __shared__ float sh[4];
    #pragma unroll
    for (int o=16;o;o>>=1) ss += __shfl_xor_sync(0xffffffffu, ss, o);
    if ((t&31)==0) sh[t>>5] = ss;
    __syncthreads();
    float inv = rsqrtf((sh[0]+sh[1]+sh[2]+sh[3])*(1.f/DM) + EPSR);
    float v[4] = {a.x*inv, a.y*inv, a.z*inv, a.w*inv};
    __nv_bfloat16 h[4], l[4];
    #pragma unroll
    for (int i=0;i<4;i++) split_bf16(v[i], h[i], l[i]);
    size_t o = (size_t)row*DM + t*4;
    __nv_bfloat162 p;
    p.x=h[0]; p.y=h[1]; *(__nv_bfloat162*)(uh+o)   = p;
    p.x=h[2]; p.y=h[3]; *(__nv_bfloat162*)(uh+o+2) = p;
    p.x=l[0]; p.y=l[1]; *(__nv_bfloat162*)(ul+o)   = p;
    p.x=l[2]; p.y=l[3]; *(__nv_bfloat162*)(ul+o+2) = p;
}

// ===================== conv + silu + mask =====================
__global__ void conv_kernel(const float* __restrict__ cw, const float* __restrict__ cb,
                            const float* __restrict__ mask){
    long idx = (long)blockIdx.x*blockDim.x + threadIdx.x;
    if (idx >= (long)NBL*CONVD) return;
    int c = (int)(idx % CONVD);
    long bl = idx / CONVD;
    int l = (int)(bl % SEQ);
    float acc = cb[c];
    #pragma unroll
    for (int i=0;i<4;i++){
        int ls = l + i - 3;
        if (ls >= 0)
            acc += g_xraw[(size_t)(bl + (i-3))*CONVD + c] * cw[c*4 + i];
    }
    g_xbc[idx] = siluf(acc) * mask[bl];
}

// ===================== bidirectional SSM scan, packed f32x2 ======================
// grid (2, NH, BATCH), 128 threads. Thread pair (2p,2p+1) owns state row p;
// each handles 32 of 64 state cols as 16 packed f32x2 pairs.
// Smem reads are broadcast (2 distinct addrs per warp) -> conflict-free.
#define CT 32
__global__ void __launch_bounds__(128) scan_kernel(const float* __restrict__ dtb,
                                                   const float* __restrict__ A_log,
                                                   const float* __restrict__ Dv,
                                                   float* __restrict__ yf,
                                                   float* __restrict__ yb){
    const int dir = blockIdx.x;
    const int h   = blockIdx.y;
    const int b   = blockIdx.z;
    const int tid = threadIdx.x;
    const int p    = tid >> 1;
    const int half = tid & 1;
    const int nbase = half << 5;   // 0 or 32
    const float Ah = -expf(A_log[h]);
    const float Dh = Dv[h];
    ull st[16];
    #pragma unroll
    for (int j=0;j<16;j++) st[j]=0ull;
    __shared__ float Bs[CT][64];
    __shared__ float Cs[CT][64];
    __shared__ float Xs[CT][64];
    __shared__ float Ts[CT];
    __shared__ float dAs[CT];
    const size_t base = (size_t)b*SEQ;
    float* yout = dir ? yb : yf;
    for (int t0=0; t0<SEQ; t0+=CT){
        for (int idx = tid; idx < CT*64; idx += 128){
            int tt = idx >> 6, pp = idx & 63;
            int t = dir ? (SEQ-1-(t0+tt)) : (t0+tt);
            size_t r = (base + t)*(size_t)CONVD;
            Bs[tt][pp] = g_xbc[r + DIN + pp];
            Cs[tt][pp] = g_xbc[r + DIN + DS + pp];
            Xs[tt][pp] = g_xbc[r + h*HD + pp];
        }
        if (tid < CT){
            int t = dir ? (SEQ-1-(t0+tid)) : (t0+tid);
            float dtv = dtb[(base + t)*NH + h];
            Ts[tid] = dtv;
            dAs[tid] = __expf(dtv*Ah);
        }
        __syncthreads();
        for (int tt=0; tt<CT; tt++){
            float dtv = Ts[tt];
            float dA  = dAs[tt];
            float xv  = Xs[tt][p];
            float dtx = dtv * xv;
            ull dA2  = pack2(dA, dA);
            ull dtx2 = pack2(dtx, dtx);
            const ull* Bp = (const ull*)(&Bs[tt][nbase]);
            const ull* Cp = (const ull*)(&Cs[tt][nbase]);
            ull ya = 0ull, yc = 0ull;
            #pragma unroll
            for (int j=0;j<16;j+=2){
                ull t0a = mul2(dtx2, Bp[j]);
                st[j] = fma2(dA2, st[j], t0a);
                ya = fma2(st[j], Cp[j], ya);
                ull t0b = mul2(dtx2, Bp[j+1]);
                st[j+1] = fma2(dA2, st[j+1], t0b);
                yc = fma2(st[j+1], Cp[j+1], yc);
            }
            ull ysum = add2(ya, yc);
            float ylo, yhi; unpack2(ysum, ylo, yhi);
            float y = ylo + yhi;
            y += __shfl_xor_sync(0xffffffffu, y, 1);
            if (half == 0){
                int t = dir ? (SEQ-1-(t0+tt)) : (t0+tt);
                float yv = y;
                if (dir==0) yv = fmaf(Dh, xv, yv);
                yout[(base + t)*(size_t)DIN + h*HD + p] = yv;
            }
        }
        __syncthreads();
    }
}

// ===================== y2 = rmsnorm((yf+yb) * silu(z)) * norm_w -> bf16 hi/lo ====
__global__ void __launch_bounds__(256) gatednorm_kernel(const float* __restrict__ z,
                                                        const float* __restrict__ w,
                                                        __nv_bfloat16* __restrict__ yh,
                                                        __nv_bfloat16* __restrict__ yl){
    int row = blockIdx.x; int t = threadIdx.x;
    float4 ya = ((const float4*)(g_yf + (size_t)row*DIN))[t];
    float4 ybv = ((const float4*)(g_yb + (size_t)row*DIN))[t];
    float4 zv = ((const float4*)(z    + (size_t)row*DIN))[t];
    float4 v;
    v.x = (ya.x + ybv.x) * siluf(zv.x);
    v.y = (ya.y + ybv.y) * siluf(zv.y);
    v.z = (ya.z + ybv.z) * siluf(zv.z);
    v.w = (ya.w + ybv.w) * siluf(zv.w);
    float ss = v.x*v.x + v.y*v.y + v.z*v.z + v.w*v.w;
    __shared__ float sh[8];
    #pragma unroll
    for (int o=16;o;o>>=1) ss += __shfl_xor_sync(0xffffffffu, ss, o);
    if ((t&31)==0) sh[t>>5] = ss;
    __syncthreads();
    float tot = sh[0]+sh[1]+sh[2]+sh[3]+sh[4]+sh[5]+sh[6]+sh[7];
    float inv = rsqrtf(tot*(1.f/DIN) + EPSR);
    float4 wv = ((const float4*)w)[t];
    float o4[4] = {v.x*inv*wv.x, v.y*inv*wv.y, v.z*inv*wv.z, v.w*inv*wv.w};
    __nv_bfloat16 h[4], l[4];
    #pragma unroll
    for (int i=0;i<4;i++) split_bf16(o4[i], h[i], l[i]);
    size_t o = (size_t)row*DIN + t*4;
    __nv_bfloat162 p;
    p.x=h[0]; p.y=h[1]; *(__nv_bfloat162*)(yh+o)   = p;
    p.x=h[2]; p.y=h[3]; *(__nv_bfloat162*)(yh+o+2) = p;
    p.x=l[0]; p.y=l[1]; *(__nv_bfloat162*)(yl+o)   = p;
    p.x=l[2]; p.y=l[3]; *(__nv_bfloat162*)(yl+o+2) = p;
}

// ===================== h = rmsnorm(2*m) -> bf16 hi/lo =====================
__global__ void __launch_bounds__(128) postnorm_kernel(const float* __restrict__ m,
                                                       __nv_bfloat16* __restrict__ hh,
                                                       __nv_bfloat16* __restrict__ hl){
    int row = blockIdx.x; int t = threadIdx.x;
    float4 mv = ((const float4*)(m + (size_t)row*DM))[t];
    float4 v = make_float4(2.f*mv.x, 2.f*mv.y, 2.f*mv.z, 2.f*mv.w);
    float ss = v.x*v.x + v.y*v.y + v.z*v.z + v.w*v.w;
    __shared__ float sh[4];
    #pragma unroll
    for (int o=16;o;o>>=1) ss += __shfl_xor_sync(0xffffffffu, ss, o);
    if ((t&31)==0) sh[t>>5] = ss;
    __syncthreads();
    float inv = rsqrtf((sh[0]+sh[1]+sh[2]+sh[3])*(1.f/DM) + EPSR);
    float o4[4] = {v.x*inv, v.y*inv, v.z*inv, v.w*inv};
    __nv_bfloat16 h[4], l[4];
    #pragma unroll
    for (int i=0;i<4;i++) split_bf16(o4[i], h[i], l[i]);
    size_t o = (size_t)row*DM + t*4;
    __nv_bfloat162 p;
    p.x=h[0]; p.y=h[1]; *(__nv_bfloat162*)(hh+o)   = p;
    p.x=h[2]; p.y=h[3]; *(__nv_bfloat162*)(hh+o+2) = p;
    p.x=l[0]; p.y=l[1]; *(__nv_bfloat162*)(hl+o)   = p;
    p.x=l[2]; p.y=l[3]; *(__nv_bfloat162*)(hl+o+2) = p;
}

extern "C" void kernel_launch(void* const* d_in, const int* in_sizes, int n_in,
                              void* d_out, int out_size){
    const float* x      = (const float*)d_in[0];
    const float* mask   = (const float*)d_in[1];
    const float* W_in   = (const float*)d_in[2];
    const float* conv_w = (const float*)d_in[3];
    const float* conv_b = (const float*)d_in[4];
    const float* dt_bias= (const float*)d_in[5];
    const float* A_log  = (const float*)d_in[6];
    const float* Dv     = (const float*)d_in[7];
    const float* norm_w = (const float*)d_in[8];
    const float* W_out  = (const float*)d_in[9];
    const float* W1     = (const float*)d_in[10];
    const float* b1     = (const float*)d_in[11];
    const float* W2     = (const float*)d_in[12];
    const float* b2     = (const float*)d_in[13];

    float* out_x  = (float*)d_out;
    float* out_m  = out_x  + (size_t)NBL*DM;
    float* out_dt = out_m  + (size_t)NBL*DM;
    float* out_z  = out_dt + (size_t)NBL*NH;

    float *pxraw, *pyf, *pyb;
    __nv_bfloat16 *puh,*pul,*py2h,*py2l,*phh,*phl,*pffh,*pffl;
    __nv_bfloat16 *pwih,*pwil,*pwoh,*pwol,*pw1h,*pw1l,*pw2h,*pw2l;
    cudaGetSymbolAddress((void**)&pxraw, g_xraw);
    cudaGetSymbolAddress((void**)&pyf,  g_yf);  cudaGetSymbolAddress((void**)&pyb,  g_yb);
    cudaGetSymbolAddress((void**)&puh,  g_uh);  cudaGetSymbolAddress((void**)&pul,  g_ul);
    cudaGetSymbolAddress((void**)&py2h, g_y2h); cudaGetSymbolAddress((void**)&py2l, g_y2l);
    cudaGetSymbolAddress((void**)&phh,  g_hh);  cudaGetSymbolAddress((void**)&phl,  g_hl);
    cudaGetSymbolAddress((void**)&pffh, g_ffh); cudaGetSymbolAddress((void**)&pffl, g_ffl);
    cudaGetSymbolAddress((void**)&pwih, g_wih); cudaGetSymbolAddress((void**)&pwil, g_wil);
    cudaGetSymbolAddress((void**)&pwoh, g_woh); cudaGetSymbolAddress((void**)&pwol, g_wol);
    cudaGetSymbolAddress((void**)&pw1h, g_w1h); cudaGetSymbolAddress((void**)&pw1l, g_w1l);
    cudaGetSymbolAddress((void**)&pw2h, g_w2h); cudaGetSymbolAddress((void**)&pw2l, g_w2l);

    cudaFuncSetAttribute(mma_gemm<0>, cudaFuncAttributeMaxDynamicSharedMemorySize, GSMEM_BYTES);
    cudaFuncSetAttribute(mma_gemm<1>, cudaFuncAttributeMaxDynamicSharedMemorySize, GSMEM_BYTES);
    cudaFuncSetAttribute(mma_gemm<2>, cudaFuncAttributeMaxDynamicSharedMemorySize, GSMEM_BYTES);
    cudaFuncSetAttribute(mma_gemm<3>, cudaFuncAttributeMaxDynamicSharedMemorySize, GSMEM_BYTES);

    dim3 wb(32,8);
    wconv_kernel<<<dim3((DPROJ+31)/32, DM/32),   wb>>>(W_in,  pwih, pwil, DM,  DPROJ);
    wconv_kernel<<<dim3((DM+31)/32,    DIN/32),  wb>>>(W_out, pwoh, pwol, DIN, DM);
    wconv_kernel<<<dim3((DFF+31)/32,   DM/32),   wb>>>(W1,    pw1h, pw1l, DM,  DFF);
    wconv_kernel<<<dim3((DM+31)/32,    DFF/32),  wb>>>(W2,    pw2h, pw2l, DFF, DM);

    // 1) pre-norm -> bf16 split
    prenorm_kernel<<<NBL,128>>>(x, mask, puh, pul);
    // 2) in-projection, fused epilogue: z -> out_z, xBC -> g_xraw, dt -> out_dt
    mma_gemm<3><<<dim3((DPROJ+127)/128, NBL/128), 256, GSMEM_BYTES>>>(
        puh, pul, pwih, pwil, DPROJ, DM, nullptr, nullptr, nullptr, nullptr, nullptr,
        out_z, pxraw, out_dt, dt_bias);
    // 3) conv + silu + mask
    conv_kernel<<<(int)(((long)NBL*CONVD + 255)/256), 256>>>(conv_w, conv_b, mask);
    // 4) bidirectional scan (no atomics: fwd->yf (+D*x), bwd->yb)
    scan_kernel<<<dim3(2,NH,BATCH), 128>>>(out_dt, A_log, Dv, pyf, pyb);
    // 5) gated rmsnorm -> bf16 split
    gatednorm_kernel<<<NBL,256>>>(out_z, norm_w, py2h, py2l);
    // 6) out projection -> m
    mma_gemm<0><<<dim3(DM/128, NBL/128), 256, GSMEM_BYTES>>>(
        py2h, py2l, pwoh, pwol, DM, DIN, out_m, nullptr, nullptr, nullptr, nullptr,
        nullptr, nullptr, nullptr, nullptr);
    // 7) h = rmsnorm(2m)
    postnorm_kernel<<<NBL,128>>>(out_m, phh, phl);
    // 8) FFN up
    mma_gemm<1><<<dim3(DFF/128, NBL/128), 256, GSMEM_BYTES>>>(
        phh, phl, pw1h, pw1l, DFF, DM, nullptr, b1, nullptr, pffh, pffl,
        nullptr, nullptr, nullptr, nullptr);
    // 9) FFN down + residual
    mma_gemm<2><<<dim3(DM/128, NBL/128), 256, GSMEM_BYTES>>>(
        pffh, pffl, pw2h, pw2l, DM, DFF, out_x, b2, out_m, nullptr, nullptr,
        nullptr, nullptr, nullptr, nullptr);
}

// round 7
// speedup vs baseline: 1.2954x; 1.2954x over previous
#include <cuda_runtime.h>
#include <cuda_fp16.h>
#include <math.h>
#include <stdint.h>

#define BATCH 8
#define SEQ   2048
#define NBL   (BATCH*SEQ)          // 16384
#define DM    512
#define DIN   1024
#define NH    16
#define HD    64
#define DS    64
#define CONVD 1152
#define DPROJ 2192
#define DFF   2048
#define EPSR  1e-6f

// ===================== scratch (static device; no cudaMalloc) =====================
static __device__ float g_xraw[(size_t)NBL*CONVD];  // in-proj xBC (pre-conv)
static __device__ float g_xbc[(size_t)NBL*CONVD];   // conv+silu output
static __device__ float g_yf[(size_t)NBL*DIN];      // forward scan out (+D*x)
static __device__ float g_yb[(size_t)NBL*DIN];      // backward scan out
// fp16 activations
static __device__ __half g_u[(size_t)NBL*DM];
static __device__ __half g_y2[(size_t)NBL*DIN];
static __device__ __half g_h[(size_t)NBL*DM];
static __device__ __half g_ff[(size_t)NBL*DFF];
// fp16 transposed weights [N,K]
static __device__ __half g_wi[(size_t)DPROJ*DM];
static __device__ __half g_wo[(size_t)DM*DIN];
static __device__ __half g_w1[(size_t)DFF*DM];
static __device__ __half g_w2[(size_t)DM*DFF];

// ===================== helpers =====================
__device__ __forceinline__ uint32_t smem_to_u32(const void* smem_ptr) {
    uint32_t addr;
    asm("{ .reg .u64 tmp; cvta.to.shared.u64 tmp, %1; cvt.u32.u64 %0, tmp; }"
        : "=r"(addr) : "l"(smem_ptr));
    return addr;
}
__device__ __forceinline__ void cp_async16(uint32_t dst, const void* src, uint32_t bytes){
    asm volatile("cp.async.cg.shared.global [%0], [%1], 16, %2;"
                 :: "r"(dst), "l"(src), "r"(bytes));
}
#define CP_COMMIT() asm volatile("cp.async.commit_group;")
#define CP_WAIT1()  asm volatile("cp.async.wait_group 1;")
#define CP_WAIT0()  asm volatile("cp.async.wait_group 0;")

__device__ __forceinline__ void ldm_x4(uint32_t addr, uint32_t& r0, uint32_t& r1,
                                       uint32_t& r2, uint32_t& r3){
    asm volatile("ldmatrix.sync.aligned.m8n8.x4.shared.b16 {%0,%1,%2,%3}, [%4];"
                 : "=r"(r0), "=r"(r1), "=r"(r2), "=r"(r3) : "r"(addr));
}
__device__ __forceinline__ void mma16816(float* c, const uint32_t* a, const uint32_t* b){
    asm volatile(
        "mma.sync.aligned.m16n8k16.row.col.f32.f16.f16.f32 "
        "{%0,%1,%2,%3}, {%4,%5,%6,%7}, {%8,%9}, {%0,%1,%2,%3};"
        : "+f"(c[0]), "+f"(c[1]), "+f"(c[2]), "+f"(c[3])
        : "r"(a[0]), "r"(a[1]), "r"(a[2]), "r"(a[3]), "r"(b[0]), "r"(b[1]));
}

__device__ __forceinline__ float siluf(float x){ return x / (1.f + expf(-x)); }
__device__ __forceinline__ float geluf(float x){
    float x3 = x*x*x;
    return 0.5f*x*(1.f + tanhf(0.7978845608028654f*(x + 0.044715f*x3)));
}
__device__ __forceinline__ float softplusf(float x){
    return fmaxf(x, 0.f) + log1pf(expf(-fabsf(x)));
}

// ===================== weight transpose: W[K,N] fp32 -> T[N,K] fp16 ==============
__global__ void wconv_kernel(const float* __restrict__ W,
                             __half* __restrict__ T, int K, int N){
    __shared__ float tile[32][33];
    int n0 = blockIdx.x*32, k0 = blockIdx.y*32;
    int tx = threadIdx.x, ty = threadIdx.y;   // 32 x 8
    #pragma unroll
    for (int i=0;i<32;i+=8){
        int k = k0+ty+i, n = n0+tx;
        tile[ty+i][tx] = (n < N) ? W[(size_t)k*N + n] : 0.f;
    }
    __syncthreads();
    #pragma unroll
    for (int i=0;i<32;i+=8){
        int n = n0+ty+i, k = k0+tx;
        if (n < N) T[(size_t)n*K + k] = __float2half(tile[tx][ty+i]);
    }
}

// ===================== fp16 HMMA GEMM ============================================
// C[M,N] = A[M,K] @ B[K,N]; A fp16 [M,K], B fp16 [N,K] (pre-transposed).
// 128x128 tile, BK=32, 3-stage cp.async pipeline, 256 threads, 2 CTAs/SM.
// MODE 0: fp32 store; MODE 1: gelu(acc+bias)->fp16; MODE 2: acc+bias+2*res->fp32
// MODE 3: in-proj fused split (z, xBC, dt)
#define BK 32
#define LDSB 80                                  // smem row stride bytes (40 elems)
#define MAT_ELEMS (128*40)
#define STAGE_BYTES (2*MAT_ELEMS*2)              // A + B = 20480
#define GSMEM_BYTES (3*STAGE_BYTES)              // 61440

template<int MODE>
__global__ void __launch_bounds__(256,2)
mma_gemm(const __half* __restrict__ A, const __half* __restrict__ B,
         int N, int K,
         float* __restrict__ C, const float* __restrict__ bias,
         const float* __restrict__ res, __half* __restrict__ Oh,
         float* __restrict__ z_out, float* __restrict__ xraw,
         float* __restrict__ dt_out, const float* __restrict__ dtb)
{
    extern __shared__ __half smem[];
    const uint32_t sb = smem_to_u32(smem);
    const int tid = threadIdx.x;
    const int lane = tid & 31, wid = tid >> 5;
    const int row0 = blockIdx.y * 128;
    const int n0   = blockIdx.x * 128;
    const int wm0 = (wid & 3) * 32;
    const int wn0 = (wid >> 2) * 64;

    const int r_a  = tid >> 2, c8 = (tid & 3) * 8;
    const uint32_t aoff = (uint32_t)((lane & 15) * LDSB + (lane >> 4) * 16);
    const uint32_t boff = (uint32_t)(((lane & 7) + ((lane & 16) >> 1)) * LDSB + (lane & 8) * 2);

    float acc[2][8][4];
    #pragma unroll
    for (int i=0;i<2;i++)
        #pragma unroll
        for (int j=0;j<8;j++)
            #pragma unroll
            for (int q=0;q<4;q++) acc[i][j][q]=0.f;

    const int nch = K / BK;

    auto issue = [&](int ch){
        const int k0 = ch * BK;
        uint32_t base = sb + (uint32_t)((ch % 3) * STAGE_BYTES);
        #pragma unroll
        for (int i=0;i<2;i++){
            int r = r_a + i*64;
            size_t g = (size_t)(row0 + r) * K + k0 + c8;
            uint32_t so = (uint32_t)(r * LDSB + c8 * 2);
            cp_async16(base + so, A + g, 16);
        }
        #pragma unroll
        for (int i=0;i<2;i++){
            int r = r_a + i*64;
            int n = n0 + r;
            int valid = (n < N);
            size_t g = (size_t)(valid ? n : 0) * K + k0 + c8;
            uint32_t so = (uint32_t)(r * LDSB + c8 * 2);
            cp_async16(base + (uint32_t)MAT_ELEMS*2 + so, B + g, valid ? 16u : 0u);
        }
        CP_COMMIT();
    };

    issue(0); issue(1);
    for (int ch = 0; ch < nch; ch++){
        if (ch + 1 < nch) CP_WAIT1(); else CP_WAIT0();
        __syncthreads();
        if (ch + 2 < nch) issue(ch + 2);

        const uint32_t base = sb + (uint32_t)((ch % 3) * STAGE_BYTES);
        const uint32_t bA = base;
        const uint32_t bB = base + (uint32_t)MAT_ELEMS*2;

        #pragma unroll
        for (int ks = 0; ks < BK; ks += 16){
            uint32_t a[2][4], b[8][2];
            #pragma unroll
            for (int mt = 0; mt < 2; mt++){
                uint32_t ao = (uint32_t)((wm0 + mt*16) * LDSB + ks*2) + aoff;
                ldm_x4(bA + ao, a[mt][0], a[mt][1], a[mt][2], a[mt][3]);
            }
            #pragma unroll
            for (int p = 0; p < 4; p++){
                uint32_t bo = (uint32_t)((wn0 + p*16) * LDSB + ks*2) + boff;
                ldm_x4(bB + bo, b[2*p][0], b[2*p][1], b[2*p+1][0], b[2*p+1][1]);
            }
            #pragma unroll
            for (int mt = 0; mt < 2; mt++)
                #pragma unroll
                for (int nt = 0; nt < 8; nt++)
                    mma16816(acc[mt][nt], a[mt], b[nt]);
        }
        __syncthreads();
    }

    const int rb = row0 + wm0 + (lane >> 2);
    const int cb = n0 + wn0 + (lane & 3) * 2;
    #pragma unroll
    for (int mt = 0; mt < 2; mt++){
        #pragma unroll
        for (int nt = 0; nt < 8; nt++){
            int c = cb + nt*8;
            if (c >= N) continue;
            #pragma unroll
            for (int half = 0; half < 2; half++){
                int r = rb + mt*16 + half*8;
                float v0 = acc[mt][nt][half*2+0];
                float v1 = acc[mt][nt][half*2+1];
                size_t o = (size_t)r*N + c;
                if (MODE == 0){
                    *(float2*)(C + o) = make_float2(v0, v1);
                } else if (MODE == 1){
                    v0 = geluf(v0 + bias[c]);
                    v1 = geluf(v1 + bias[c+1]);
                    __half2 hp; hp.x = __float2half(v0); hp.y = __float2half(v1);
                    *(__half2*)(Oh + o) = hp;
                } else if (MODE == 2){
                    float2 rv = *(const float2*)(res + o);
                    *(float2*)(C + o) = make_float2(v0 + bias[c]   + 2.f*rv.x,
                                                    v1 + bias[c+1] + 2.f*rv.y);
                } else {
                    if (c < DIN){
                        *(float2*)(z_out + (size_t)r*DIN + c) = make_float2(v0, v1);
                    } else if (c < DIN + CONVD){
                        *(float2*)(xraw + (size_t)r*CONVD + (c - DIN)) = make_float2(v0, v1);
                    } else {
                        int hh2 = c - (DIN + CONVD);
                        dt_out[(size_t)r*NH + hh2]     = softplusf(v0 + dtb[hh2]);
                        dt_out[(size_t)r*NH + hh2 + 1] = softplusf(v1 + dtb[hh2+1]);
                    }
                }
            }
        }
    }
}

// ===================== u = rmsnorm(x*mask) -> fp16 =====================
__global__ void __launch_bounds__(128) prenorm_kernel(const float* __restrict__ x,
                                                      const float* __restrict__ mask,
                                                      __half* __restrict__ u){
    int row = blockIdx.x; int t = threadIdx.x;
    float mk = mask[row];
    float4 a = ((const float4*)(x + (size_t)row*DM))[t];
    a.x*=mk; a.y*=mk; a.z*=mk; a.w*=mk;
    float ss = a.x*a.x + a.y*a.y + a.z*a.z + a.w*a.w;
    __shared__ float sh[4];
    #pragma unroll
    for (int o=16;o;o>>=1) ss += __shfl_xor_sync(0xffffffffu, ss, o);
    if ((t&31)==0) sh[t>>5] = ss;
    __syncthreads();
    float inv = rsqrtf((sh[0]+sh[1]+sh[2]+sh[3])*(1.f/DM) + EPSR);
    __half2 p0, p1;
    p0.x = __float2half(a.x*inv); p0.y = __float2half(a.y*inv);
    p1.x = __float2half(a.z*inv); p1.y = __float2half(a.w*inv);
    size_t o = (size_t)row*DM + t*4;
    *(__half2*)(u+o)   = p0;
    *(__half2*)(u+o+2) = p1;
}

// ===================== conv + silu + mask =====================
__global__ void conv_kernel(const float* __restrict__ cw, const float* __restrict__ cb,
                            const float* __restrict__ mask){
    long idx = (long)blockIdx.x*blockDim.x + threadIdx.x;
    if (idx >= (long)NBL*CONVD) return;
    int c = (int)(idx % CONVD);
    long bl = idx / CONVD;
    int l = (int)(bl % SEQ);
    float acc = cb[c];
    #pragma unroll
    for (int i=0;i<4;i++){
        int ls = l + i - 3;
        if (ls >= 0)
            acc += g_xraw[(size_t)(bl + (i-3))*CONVD + c] * cw[c*4 + i];
    }
    g_xbc[idx] = siluf(acc) * mask[bl];
}

// ===================== bidirectional SSM scan (scalar, no atomics) ===============
// grid (2, NH, BATCH), 128 threads. Thread pair (2p,2p+1) owns state row p;
// each handles 32 of 64 state cols (odd half rotated by 16).
#define CT 32
__global__ void __launch_bounds__(128) scan_kernel(const float* __restrict__ dtb,
                                                   const float* __restrict__ A_log,
                                                   const float* __restrict__ Dv,
                                                   float* __restrict__ yf,
                                                   float* __restrict__ yb){
    const int dir = blockIdx.x;
    const int h   = blockIdx.y;
    const int b   = blockIdx.z;
    const int tid = threadIdx.x;
    const int p    = tid >> 1;
    const int half = tid & 1;
    const int nbase = half << 5;   // 0 or 32
    const int rot   = half << 4;   // 0 or 16
    const float Ah = -expf(A_log[h]);
    const float Dh = Dv[h];
    float st[32];
    #pragma unroll
    for (int j=0;j<32;j++) st[j]=0.f;
    __shared__ float Bs[CT][64];
    __shared__ float Cs[CT][64];
    __shared__ float Xs[CT][64];
    __shared__ float Ts[CT];
    __shared__ float dAs[CT];
    const size_t base = (size_t)b*SEQ;
    float* yout = dir ? yb : yf;
    for (int t0=0; t0<SEQ; t0+=CT){
        for (int idx = tid; idx < CT*64; idx += 128){
            int tt = idx >> 6, pp = idx & 63;
            int t = dir ? (SEQ-1-(t0+tt)) : (t0+tt);
            size_t r = (base + t)*(size_t)CONVD;
            Bs[tt][pp] = g_xbc[r + DIN + pp];
            Cs[tt][pp] = g_xbc[r + DIN + DS + pp];
            Xs[tt][pp] = g_xbc[r + h*HD + pp];
        }
        if (tid < CT){
            int t = dir ? (SEQ-1-(t0+tid)) : (t0+tid);
            float dtv = dtb[(base + t)*NH + h];
            Ts[tid] = dtv;
            dAs[tid] = __expf(dtv*Ah);
        }
        __syncthreads();
        for (int tt=0; tt<CT; tt++){
            float dtv = Ts[tt];
            float dA  = dAs[tt];
            float xv  = Xs[tt][p];
            float dtx = dtv * xv;
            float y0=0.f, y1=0.f;
            #pragma unroll
            for (int j=0;j<32;j+=2){
                int na = nbase + ((j   + rot) & 31);
                int nb2= nbase + ((j+1 + rot) & 31);
                st[j]   = fmaf(dA, st[j],   dtx*Bs[tt][na]);
                y0 = fmaf(st[j],   Cs[tt][na], y0);
                st[j+1] = fmaf(dA, st[j+1], dtx*Bs[tt][nb2]);
                y1 = fmaf(st[j+1], Cs[tt][nb2], y1);
            }
            float y = y0 + y1;
            y += __shfl_xor_sync(0xffffffffu, y, 1);
            if (half == 0){
                int t = dir ? (SEQ-1-(t0+tt)) : (t0+tt);
                float yv = y;
                if (dir==0) yv = fmaf(Dh, xv, yv);
                yout[(base + t)*(size_t)DIN + h*HD + p] = yv;
            }
        }
        __syncthreads();
    }
}

// ===================== y2 = rmsnorm((yf+yb) * silu(z)) * norm_w -> fp16 ==========
__global__ void __launch_bounds__(256) gatednorm_kernel(const float* __restrict__ z,
                                                        const float* __restrict__ w,
                                                        __half* __restrict__ y2){
    int row = blockIdx.x; int t = threadIdx.x;
    float4 ya = ((const float4*)(g_yf + (size_t)row*DIN))[t];
    float4 ybv = ((const float4*)(g_yb + (size_t)row*DIN))[t];
    float4 zv = ((const float4*)(z    + (size_t)row*DIN))[t];
    float4 v;
    v.x = (ya.x + ybv.x) * siluf(zv.x);
    v.y = (ya.y + ybv.y) * siluf(zv.y);
    v.z = (ya.z + ybv.z) * siluf(zv.z);
    v.w = (ya.w + ybv.w) * siluf(zv.w);
    float ss = v.x*v.x + v.y*v.y + v.z*v.z + v.w*v.w;
    __shared__ float sh[8];
    #pragma unroll
    for (int o=16;o;o>>=1) ss += __shfl_xor_sync(0xffffffffu, ss, o);
    if ((t&31)==0) sh[t>>5] = ss;
    __syncthreads();
    float tot = sh[0]+sh[1]+sh[2]+sh[3]+sh[4]+sh[5]+sh[6]+sh[7];
    float inv = rsqrtf(tot*(1.f/DIN) + EPSR);
    float4 wv = ((const float4*)w)[t];
    __half2 p0, p1;
    p0.x = __float2half(v.x*inv*wv.x); p0.y = __float2half(v.y*inv*wv.y);
    p1.x = __float2half(v.z*inv*wv.z); p1.y = __float2half(v.w*inv*wv.w);
    size_t o = (size_t)row*DIN + t*4;
    *(__half2*)(y2+o)   = p0;
    *(__half2*)(y2+o+2) = p1;
}

// ===================== h = rmsnorm(2*m) -> fp16 =====================
__global__ void __launch_bounds__(128) postnorm_kernel(const float* __restrict__ m,
                                                       __half* __restrict__ hbuf){
    int row = blockIdx.x; int t = threadIdx.x;
    float4 mv = ((const float4*)(m + (size_t)row*DM))[t];
    float4 v = make_float4(2.f*mv.x, 2.f*mv.y, 2.f*mv.z, 2.f*mv.w);
    float ss = v.x*v.x + v.y*v.y + v.z*v.z + v.w*v.w;
    __shared__ float sh[4];
    #pragma unroll
    for (int o=16;o;o>>=1) ss += __shfl_xor_sync(0xffffffffu, ss, o);
    if ((t&31)==0) sh[t>>5] = ss;
    __syncthreads();
    float inv = rsqrtf((sh[0]+sh[1]+sh[2]+sh[3])*(1.f/DM) + EPSR);
    __half2 p0, p1;
    p0.x = __float2half(v.x*inv); p0.y = __float2half(v.y*inv);
    p1.x = __float2half(v.z*inv); p1.y = __float2half(v.w*inv);
    size_t o = (size_t)row*DM + t*4;
    *(__half2*)(hbuf+o)   = p0;
    *(__half2*)(hbuf+o+2) = p1;
}

extern "C" void kernel_launch(void* const* d_in, const int* in_sizes, int n_in,
                              void* d_out, int out_size){
    const float* x      = (const float*)d_in[0];
    const float* mask   = (const float*)d_in[1];
    const float* W_in   = (const float*)d_in[2];
    const float* conv_w = (const float*)d_in[3];
    const float* conv_b = (const float*)d_in[4];
    const float* dt_bias= (const float*)d_in[5];
    const float* A_log  = (const float*)d_in[6];
    const float* Dv     = (const float*)d_in[7];
    const float* norm_w = (const float*)d_in[8];
    const float* W_out  = (const float*)d_in[9];
    const float* W1     = (const float*)d_in[10];
    const float* b1     = (const float*)d_in[11];
    const float* W2     = (const float*)d_in[12];
    const float* b2     = (const float*)d_in[13];

    float* out_x  = (float*)d_out;
    float* out_m  = out_x  + (size_t)NBL*DM;
    float* out_dt = out_m  + (size_t)NBL*DM;
    float* out_z  = out_dt + (size_t)NBL*NH;

    float *pxraw, *pyf, *pyb;
    __half *pu, *py2, *ph, *pff, *pwi, *pwo, *pw1, *pw2;
    cudaGetSymbolAddress((void**)&pxraw, g_xraw);
    cudaGetSymbolAddress((void**)&pyf, g_yf); cudaGetSymbolAddress((void**)&pyb, g_yb);
    cudaGetSymbolAddress((void**)&pu,  g_u);  cudaGetSymbolAddress((void**)&py2, g_y2);
    cudaGetSymbolAddress((void**)&ph,  g_h);  cudaGetSymbolAddress((void**)&pff, g_ff);
    cudaGetSymbolAddress((void**)&pwi, g_wi); cudaGetSymbolAddress((void**)&pwo, g_wo);
    cudaGetSymbolAddress((void**)&pw1, g_w1); cudaGetSymbolAddress((void**)&pw2, g_w2);

    cudaFuncSetAttribute(mma_gemm<0>, cudaFuncAttributeMaxDynamicSharedMemorySize, GSMEM_BYTES);
    cudaFuncSetAttribute(mma_gemm<1>, cudaFuncAttributeMaxDynamicSharedMemorySize, GSMEM_BYTES);
    cudaFuncSetAttribute(mma_gemm<2>, cudaFuncAttributeMaxDynamicSharedMemorySize, GSMEM_BYTES);
    cudaFuncSetAttribute(mma_gemm<3>, cudaFuncAttributeMaxDynamicSharedMemorySize, GSMEM_BYTES);

    dim3 wb(32,8);
    wconv_kernel<<<dim3((DPROJ+31)/32, DM/32),  wb>>>(W_in,  pwi, DM,  DPROJ);
    wconv_kernel<<<dim3((DM+31)/32,    DIN/32), wb>>>(W_out, pwo, DIN, DM);
    wconv_kernel<<<dim3((DFF+31)/32,   DM/32),  wb>>>(W1,    pw1, DM,  DFF);
    wconv_kernel<<<dim3((DM+31)/32,    DFF/32), wb>>>(W2,    pw2, DFF, DM);

    // 1) pre-norm -> fp16
    prenorm_kernel<<<NBL,128>>>(x, mask, pu);
    // 2) in-projection, fused epilogue: z -> out_z, xBC -> g_xraw, dt -> out_dt
    mma_gemm<3><<<dim3((DPROJ+127)/128, NBL/128), 256, GSMEM_BYTES>>>(
        pu, pwi, DPROJ, DM, nullptr, nullptr, nullptr, nullptr,
        out_z, pxraw, out_dt, dt_bias);
    // 3) conv + silu + mask
    conv_kernel<<<(int)(((long)NBL*CONVD + 255)/256), 256>>>(conv_w, conv_b, mask);
    // 4) bidirectional scan (no atomics)
    scan_kernel<<<dim3(2,NH,BATCH), 128>>>(out_dt, A_log, Dv, pyf, pyb);
    // 5) gated rmsnorm -> fp16
    gatednorm_kernel<<<NBL,256>>>(out_z, norm_w, py2);
    // 6) out projection -> m
    mma_gemm<0><<<dim3(DM/128, NBL/128), 256, GSMEM_BYTES>>>(
        py2, pwo, DM, DIN, out_m, nullptr, nullptr, nullptr,
        nullptr, nullptr, nullptr, nullptr);
    // 7) h = rmsnorm(2m) -> fp16
    postnorm_kernel<<<NBL,128>>>(out_m, ph);
    // 8) FFN up: gelu -> fp16
    mma_gemm<1><<<dim3(DFF/128, NBL/128), 256, GSMEM_BYTES>>>(
        ph, pw1, DFF, DM, nullptr, b1, nullptr, pff,
        nullptr, nullptr, nullptr, nullptr);
    // 9) FFN down + residual
    mma_gemm<2><<<dim3(DM/128, NBL/128), 256, GSMEM_BYTES>>>(
        pff, pw2, DM, DFF, out_x, b2, out_m, nullptr,
        nullptr, nullptr, nullptr, nullptr);
}

// round 8
// speedup vs baseline: 1.3195x; 1.0186x over previous
#include <cuda_runtime.h>
#include <cuda_fp16.h>
#include <math.h>
#include <stdint.h>

#define BATCH 8
#define SEQ   2048
#define NBL   (BATCH*SEQ)          // 16384
#define DM    512
#define DIN   1024
#define NH    16
#define HD    64
#define DS    64
#define CONVD 1152
#define DPROJ 2192
#define DFF   2048
#define EPSR  1e-6f

// ===================== scratch (static device; no cudaMalloc) =====================
static __device__ float g_xraw[(size_t)NBL*CONVD];  // in-proj xBC (pre-conv)
static __device__ float g_xbc[(size_t)NBL*CONVD];   // conv+silu output
static __device__ float g_yf[(size_t)NBL*DIN];      // forward scan out (+D*x)
static __device__ float g_yb[(size_t)NBL*DIN];      // backward scan out
// fp16 activations
static __device__ __half g_u[(size_t)NBL*DM];
static __device__ __half g_y2[(size_t)NBL*DIN];
static __device__ __half g_h[(size_t)NBL*DM];
static __device__ __half g_ff[(size_t)NBL*DFF];
// fp16 transposed weights [N,K]
static __device__ __half g_wi[(size_t)DPROJ*DM];
static __device__ __half g_wo[(size_t)DM*DIN];
static __device__ __half g_w1[(size_t)DFF*DM];
static __device__ __half g_w2[(size_t)DM*DFF];

// ===================== helpers =====================
__device__ __forceinline__ uint32_t smem_to_u32(const void* smem_ptr) {
    uint32_t addr;
    asm("{ .reg .u64 tmp; cvta.to.shared.u64 tmp, %1; cvt.u32.u64 %0, tmp; }"
        : "=r"(addr) : "l"(smem_ptr));
    return addr;
}
__device__ __forceinline__ void cp_async16(uint32_t dst, const void* src, uint32_t bytes){
    asm volatile("cp.async.cg.shared.global [%0], [%1], 16, %2;"
                 :: "r"(dst), "l"(src), "r"(bytes));
}
#define CP_COMMIT() asm volatile("cp.async.commit_group;")
#define CP_WAIT1()  asm volatile("cp.async.wait_group 1;")
#define CP_WAIT0()  asm volatile("cp.async.wait_group 0;")

__device__ __forceinline__ void ldm_x4(uint32_t addr, uint32_t& r0, uint32_t& r1,
                                       uint32_t& r2, uint32_t& r3){
    asm volatile("ldmatrix.sync.aligned.m8n8.x4.shared.b16 {%0,%1,%2,%3}, [%4];"
                 : "=r"(r0), "=r"(r1), "=r"(r2), "=r"(r3) : "r"(addr));
}
__device__ __forceinline__ void mma16816(float* c, const uint32_t* a, const uint32_t* b){
    asm volatile(
        "mma.sync.aligned.m16n8k16.row.col.f32.f16.f16.f32 "
        "{%0,%1,%2,%3}, {%4,%5,%6,%7}, {%8,%9}, {%0,%1,%2,%3};"
        : "+f"(c[0]), "+f"(c[1]), "+f"(c[2]), "+f"(c[3])
        : "r"(a[0]), "r"(a[1]), "r"(a[2]), "r"(a[3]), "r"(b[0]), "r"(b[1]));
}

__device__ __forceinline__ float siluf(float x){ return x / (1.f + expf(-x)); }
__device__ __forceinline__ float geluf(float x){
    float x3 = x*x*x;
    return 0.5f*x*(1.f + tanhf(0.7978845608028654f*(x + 0.044715f*x3)));
}
__device__ __forceinline__ float softplusf(float x){
    return fmaxf(x, 0.f) + log1pf(expf(-fabsf(x)));
}

// ===================== weight transpose: W[K,N] fp32 -> T[N,K] fp16 ==============
__global__ void wconv_kernel(const float* __restrict__ W,
                             __half* __restrict__ T, int K, int N){
    __shared__ float tile[32][33];
    int n0 = blockIdx.x*32, k0 = blockIdx.y*32;
    int tx = threadIdx.x, ty = threadIdx.y;   // 32 x 8
    #pragma unroll
    for (int i=0;i<32;i+=8){
        int k = k0+ty+i, n = n0+tx;
        tile[ty+i][tx] = (n < N) ? W[(size_t)k*N + n] : 0.f;
    }
    __syncthreads();
    #pragma unroll
    for (int i=0;i<32;i+=8){
        int n = n0+ty+i, k = k0+tx;
        if (n < N) T[(size_t)n*K + k] = __float2half(tile[tx][ty+i]);
    }
}

// ===================== fp16 HMMA GEMM, BK=64 =====================================
// C[M,N] = A[M,K] @ B[K,N]; A fp16 [M,K], B fp16 [N,K] (pre-transposed).
// 128x128 tile, BK=64, 3-stage cp.async pipeline, 256 threads, 2 CTAs/SM.
// MODE 0: fp32 store; MODE 1: gelu(acc+bias)->fp16; MODE 2: acc+bias+2*res->fp32
// MODE 3: in-proj fused split (z, xBC, dt)
#define BK 64
#define LDSB 144                                 // smem row stride bytes (72 elems)
#define MAT_ELEMS (128*72)                       // 9216 elems per matrix per stage
#define STAGE_BYTES (2*MAT_ELEMS*2)              // A + B = 36864
#define GSMEM_BYTES (3*STAGE_BYTES)              // 110592

template<int MODE>
__global__ void __launch_bounds__(256,2)
mma_gemm(const __half* __restrict__ A, const __half* __restrict__ B,
         int N, int K,
         float* __restrict__ C, const float* __restrict__ bias,
         const float* __restrict__ res, __half* __restrict__ Oh,
         float* __restrict__ z_out, float* __restrict__ xraw,
         float* __restrict__ dt_out, const float* __restrict__ dtb)
{
    extern __shared__ __half smem[];
    const uint32_t sb = smem_to_u32(smem);
    const int tid = threadIdx.x;
    const int lane = tid & 31, wid = tid >> 5;
    const int row0 = blockIdx.y * 128;
    const int n0   = blockIdx.x * 128;
    const int wm0 = (wid & 3) * 32;
    const int wn0 = (wid >> 2) * 64;

    // cp.async coords: 1024 16B-ops per matrix per chunk; thread does 4 for A, 4 for B
    const uint32_t aoff = (uint32_t)((lane & 15) * LDSB + (lane >> 4) * 16);
    const uint32_t boff = (uint32_t)(((lane & 7) + ((lane & 16) >> 1)) * LDSB + (lane & 8) * 2);

    float acc[2][8][4];
    #pragma unroll
    for (int i=0;i<2;i++)
        #pragma unroll
        for (int j=0;j<8;j++)
            #pragma unroll
            for (int q=0;q<4;q++) acc[i][j][q]=0.f;

    const int nch = K / BK;

    auto issue = [&](int ch){
        const int k0 = ch * BK;
        uint32_t base = sb + (uint32_t)((ch % 3) * STAGE_BYTES);
        #pragma unroll
        for (int i=0;i<4;i++){
            int id = tid + i*256;           // 0..1023
            int r = id >> 3, c8e = (id & 7) * 8;   // row, elem offset
            size_t g = (size_t)(row0 + r) * K + k0 + c8e;
            uint32_t so = (uint32_t)(r * LDSB + c8e * 2);
            cp_async16(base + so, A + g, 16);
        }
        #pragma unroll
        for (int i=0;i<4;i++){
            int id = tid + i*256;
            int r = id >> 3, c8e = (id & 7) * 8;
            int n = n0 + r;
            int valid = (n < N);
            size_t g = (size_t)(valid ? n : 0) * K + k0 + c8e;
            uint32_t so = (uint32_t)(r * LDSB + c8e * 2);
            cp_async16(base + (uint32_t)MAT_ELEMS*2 + so, B + g, valid ? 16u : 0u);
        }
        CP_COMMIT();
    };

    issue(0); if (nch > 1) issue(1);
    for (int ch = 0; ch < nch; ch++){
        if (ch + 1 < nch) CP_WAIT1(); else CP_WAIT0();
        __syncthreads();
        if (ch + 2 < nch) issue(ch + 2);

        const uint32_t base = sb + (uint32_t)((ch % 3) * STAGE_BYTES);
        const uint32_t bA = base;
        const uint32_t bB = base + (uint32_t)MAT_ELEMS*2;

        #pragma unroll
        for (int ks = 0; ks < BK; ks += 16){
            uint32_t a[2][4], b[8][2];
            #pragma unroll
            for (int mt = 0; mt < 2; mt++){
                uint32_t ao = (uint32_t)((wm0 + mt*16) * LDSB + ks*2) + aoff;
                ldm_x4(bA + ao, a[mt][0], a[mt][1], a[mt][2], a[mt][3]);
            }
            #pragma unroll
            for (int p = 0; p < 4; p++){
                uint32_t bo = (uint32_t)((wn0 + p*16) * LDSB + ks*2) + boff;
                ldm_x4(bB + bo, b[2*p][0], b[2*p][1], b[2*p+1][0], b[2*p+1][1]);
            }
            #pragma unroll
            for (int mt = 0; mt < 2; mt++)
                #pragma unroll
                for (int nt = 0; nt < 8; nt++)
                    mma16816(acc[mt][nt], a[mt], b[nt]);
        }
        __syncthreads();
    }

    const int rb = row0 + wm0 + (lane >> 2);
    const int cb = n0 + wn0 + (lane & 3) * 2;
    #pragma unroll
    for (int mt = 0; mt < 2; mt++){
        #pragma unroll
        for (int nt = 0; nt < 8; nt++){
            int c = cb + nt*8;
            if (c >= N) continue;
            #pragma unroll
            for (int half = 0; half < 2; half++){
                int r = rb + mt*16 + half*8;
                float v0 = acc[mt][nt][half*2+0];
                float v1 = acc[mt][nt][half*2+1];
                size_t o = (size_t)r*N + c;
                if (MODE == 0){
                    *(float2*)(C + o) = make_float2(v0, v1);
                } else if (MODE == 1){
                    v0 = geluf(v0 + bias[c]);
                    v1 = geluf(v1 + bias[c+1]);
                    __half2 hp; hp.x = __float2half(v0); hp.y = __float2half(v1);
                    *(__half2*)(Oh + o) = hp;
                } else if (MODE == 2){
                    float2 rv = *(const float2*)(res + o);
                    *(float2*)(C + o) = make_float2(v0 + bias[c]   + 2.f*rv.x,
                                                    v1 + bias[c+1] + 2.f*rv.y);
                } else {
                    if (c < DIN){
                        *(float2*)(z_out + (size_t)r*DIN + c) = make_float2(v0, v1);
                    } else if (c < DIN + CONVD){
                        *(float2*)(xraw + (size_t)r*CONVD + (c - DIN)) = make_float2(v0, v1);
                    } else {
                        int hh2 = c - (DIN + CONVD);
                        dt_out[(size_t)r*NH + hh2]     = softplusf(v0 + dtb[hh2]);
                        dt_out[(size_t)r*NH + hh2 + 1] = softplusf(v1 + dtb[hh2+1]);
                    }
                }
            }
        }
    }
}

// ===================== u = rmsnorm(x*mask) -> fp16 =====================
__global__ void __launch_bounds__(128) prenorm_kernel(const float* __restrict__ x,
                                                      const float* __restrict__ mask,
                                                      __half* __restrict__ u){
    int row = blockIdx.x; int t = threadIdx.x;
    float mk = mask[row];
    float4 a = ((const float4*)(x + (size_t)row*DM))[t];
    a.x*=mk; a.y*=mk; a.z*=mk; a.w*=mk;
    float ss = a.x*a.x + a.y*a.y + a.z*a.z + a.w*a.w;
    __shared__ float sh[4];
    #pragma unroll
    for (int o=16;o;o>>=1) ss += __shfl_xor_sync(0xffffffffu, ss, o);
    if ((t&31)==0) sh[t>>5] = ss;
    __syncthreads();
    float inv = rsqrtf((sh[0]+sh[1]+sh[2]+sh[3])*(1.f/DM) + EPSR);
    __half2 p0, p1;
    p0.x = __float2half(a.x*inv); p0.y = __float2half(a.y*inv);
    p1.x = __float2half(a.z*inv); p1.y = __float2half(a.w*inv);
    size_t o = (size_t)row*DM + t*4;
    *(__half2*)(u+o)   = p0;
    *(__half2*)(u+o+2) = p1;
}

// ===================== conv + silu + mask =====================
__global__ void conv_kernel(const float* __restrict__ cw, const float* __restrict__ cb,
                            const float* __restrict__ mask){
    long idx = (long)blockIdx.x*blockDim.x + threadIdx.x;
    if (idx >= (long)NBL*CONVD) return;
    int c = (int)(idx % CONVD);
    long bl = idx / CONVD;
    int l = (int)(bl % SEQ);
    float acc = cb[c];
    #pragma unroll
    for (int i=0;i<4;i++){
        int ls = l + i - 3;
        if (ls >= 0)
            acc += g_xraw[(size_t)(bl + (i-3))*CONVD + c] * cw[c*4 + i];
    }
    g_xbc[idx] = siluf(acc) * mask[bl];
}

// ===================== bidirectional SSM scan (scalar, no atomics) ===============
#define CT 32
__global__ void __launch_bounds__(128) scan_kernel(const float* __restrict__ dtb,
                                                   const float* __restrict__ A_log,
                                                   const float* __restrict__ Dv,
                                                   float* __restrict__ yf,
                                                   float* __restrict__ yb){
    const int dir = blockIdx.x;
    const int h   = blockIdx.y;
    const int b   = blockIdx.z;
    const int tid = threadIdx.x;
    const int p    = tid >> 1;
    const int half = tid & 1;
    const int nbase = half << 5;
    const int rot   = half << 4;
    const float Ah = -expf(A_log[h]);
    const float Dh = Dv[h];
    float st[32];
    #pragma unroll
    for (int j=0;j<32;j++) st[j]=0.f;
    __shared__ float Bs[CT][64];
    __shared__ float Cs[CT][64];
    __shared__ float Xs[CT][64];
    __shared__ float Ts[CT];
    __shared__ float dAs[CT];
    const size_t base = (size_t)b*SEQ;
    float* yout = dir ? yb : yf;
    for (int t0=0; t0<SEQ; t0+=CT){
        for (int idx = tid; idx < CT*64; idx += 128){
            int tt = idx >> 6, pp = idx & 63;
            int t = dir ? (SEQ-1-(t0+tt)) : (t0+tt);
            size_t r = (base + t)*(size_t)CONVD;
            Bs[tt][pp] = g_xbc[r + DIN + pp];
            Cs[tt][pp] = g_xbc[r + DIN + DS + pp];
            Xs[tt][pp] = g_xbc[r + h*HD + pp];
        }
        if (tid < CT){
            int t = dir ? (SEQ-1-(t0+tid)) : (t0+tid);
            float dtv = dtb[(base + t)*NH + h];
            Ts[tid] = dtv;
            dAs[tid] = __expf(dtv*Ah);
        }
        __syncthreads();
        for (int tt=0; tt<CT; tt++){
            float dtv = Ts[tt];
            float dA  = dAs[tt];
            float xv  = Xs[tt][p];
            float dtx = dtv * xv;
            float y0=0.f, y1=0.f;
            #pragma unroll
            for (int j=0;j<32;j+=2){
                int na = nbase + ((j   + rot) & 31);
                int nb2= nbase + ((j+1 + rot) & 31);
                st[j]   = fmaf(dA, st[j],   dtx*Bs[tt][na]);
                y0 = fmaf(st[j],   Cs[tt][na], y0);
                st[j+1] = fmaf(dA, st[j+1], dtx*Bs[tt][nb2]);
                y1 = fmaf(st[j+1], Cs[tt][nb2], y1);
            }
            float y = y0 + y1;
            y += __shfl_xor_sync(0xffffffffu, y, 1);
            if (half == 0){
                int t = dir ? (SEQ-1-(t0+tt)) : (t0+tt);
                float yv = y;
                if (dir==0) yv = fmaf(Dh, xv, yv);
                yout[(base + t)*(size_t)DIN + h*HD + p] = yv;
            }
        }
        __syncthreads();
    }
}

// ===================== y2 = rmsnorm((yf+yb) * silu(z)) * norm_w -> fp16 ==========
__global__ void __launch_bounds__(256) gatednorm_kernel(const float* __restrict__ z,
                                                        const float* __restrict__ w,
                                                        __half* __restrict__ y2){
    int row = blockIdx.x; int t = threadIdx.x;
    float4 ya = ((const float4*)(g_yf + (size_t)row*DIN))[t];
    float4 ybv = ((const float4*)(g_yb + (size_t)row*DIN))[t];
    float4 zv = ((const float4*)(z    + (size_t)row*DIN))[t];
    float4 v;
    v.x = (ya.x + ybv.x) * siluf(zv.x);
    v.y = (ya.y + ybv.y) * siluf(zv.y);
    v.z = (ya.z + ybv.z) * siluf(zv.z);
    v.w = (ya.w + ybv.w) * siluf(zv.w);
    float ss = v.x*v.x + v.y*v.y + v.z*v.z + v.w*v.w;
    __shared__ float sh[8];
    #pragma unroll
    for (int o=16;o;o>>=1) ss += __shfl_xor_sync(0xffffffffu, ss, o);
    if ((t&31)==0) sh[t>>5] = ss;
    __syncthreads();
    float tot = sh[0]+sh[1]+sh[2]+sh[3]+sh[4]+sh[5]+sh[6]+sh[7];
    float inv = rsqrtf(tot*(1.f/DIN) + EPSR);
    float4 wv = ((const float4*)w)[t];
    __half2 p0, p1;
    p0.x = __float2half(v.x*inv*wv.x); p0.y = __float2half(v.y*inv*wv.y);
    p1.x = __float2half(v.z*inv*wv.z); p1.y = __float2half(v.w*inv*wv.w);
    size_t o = (size_t)row*DIN + t*4;
    *(__half2*)(y2+o)   = p0;
    *(__half2*)(y2+o+2) = p1;
}

// ===================== h = rmsnorm(2*m) -> fp16 =====================
__global__ void __launch_bounds__(128) postnorm_kernel(const float* __restrict__ m,
                                                       __half* __restrict__ hbuf){
    int row = blockIdx.x; int t = threadIdx.x;
    float4 mv = ((const float4*)(m + (size_t)row*DM))[t];
    float4 v = make_float4(2.f*mv.x, 2.f*mv.y, 2.f*mv.z, 2.f*mv.w);
    float ss = v.x*v.x + v.y*v.y + v.z*v.z + v.w*v.w;
    __shared__ float sh[4];
    #pragma unroll
    for (int o=16;o;o>>=1) ss += __shfl_xor_sync(0xffffffffu, ss, o);
    if ((t&31)==0) sh[t>>5] = ss;
    __syncthreads();
    float inv = rsqrtf((sh[0]+sh[1]+sh[2]+sh[3])*(1.f/DM) + EPSR);
    __half2 p0, p1;
    p0.x = __float2half(v.x*inv); p0.y = __float2half(v.y*inv);
    p1.x = __float2half(v.z*inv); p1.y = __float2half(v.w*inv);
    size_t o = (size_t)row*DM + t*4;
    *(__half2*)(hbuf+o)   = p0;
    *(__half2*)(hbuf+o+2) = p1;
}

extern "C" void kernel_launch(void* const* d_in, const int* in_sizes, int n_in,
                              void* d_out, int out_size){
    const float* x      = (const float*)d_in[0];
    const float* mask   = (const float*)d_in[1];
    const float* W_in   = (const float*)d_in[2];
    const float* conv_w = (const float*)d_in[3];
    const float* conv_b = (const float*)d_in[4];
    const float* dt_bias= (const float*)d_in[5];
    const float* A_log  = (const float*)d_in[6];
    const float* Dv     = (const float*)d_in[7];
    const float* norm_w = (const float*)d_in[8];
    const float* W_out  = (const float*)d_in[9];
    const float* W1     = (const float*)d_in[10];
    const float* b1     = (const float*)d_in[11];
    const float* W2     = (const float*)d_in[12];
    const float* b2     = (const float*)d_in[13];

    float* out_x  = (float*)d_out;
    float* out_m  = out_x  + (size_t)NBL*DM;
    float* out_dt = out_m  + (size_t)NBL*DM;
    float* out_z  = out_dt + (size_t)NBL*NH;

    float *pxraw, *pyf, *pyb;
    __half *pu, *py2, *ph, *pff, *pwi, *pwo, *pw1, *pw2;
    cudaGetSymbolAddress((void**)&pxraw, g_xraw);
    cudaGetSymbolAddress((void**)&pyf, g_yf); cudaGetSymbolAddress((void**)&pyb, g_yb);
    cudaGetSymbolAddress((void**)&pu,  g_u);  cudaGetSymbolAddress((void**)&py2, g_y2);
    cudaGetSymbolAddress((void**)&ph,  g_h);  cudaGetSymbolAddress((void**)&pff, g_ff);
    cudaGetSymbolAddress((void**)&pwi, g_wi); cudaGetSymbolAddress((void**)&pwo, g_wo);
    cudaGetSymbolAddress((void**)&pw1, g_w1); cudaGetSymbolAddress((void**)&pw2, g_w2);

    cudaFuncSetAttribute(mma_gemm<0>, cudaFuncAttributeMaxDynamicSharedMemorySize, GSMEM_BYTES);
    cudaFuncSetAttribute(mma_gemm<1>, cudaFuncAttributeMaxDynamicSharedMemorySize, GSMEM_BYTES);
    cudaFuncSetAttribute(mma_gemm<2>, cudaFuncAttributeMaxDynamicSharedMemorySize, GSMEM_BYTES);
    cudaFuncSetAttribute(mma_gemm<3>, cudaFuncAttributeMaxDynamicSharedMemorySize, GSMEM_BYTES);

    dim3 wb(32,8);
    // Launch order arranged so the profiled slot (4th kernel) = in-proj GEMM.
    // 1) W_in transpose
    wconv_kernel<<<dim3((DPROJ+31)/32, DM/32),  wb>>>(W_in,  pwi, DM,  DPROJ);
    // 2) pre-norm -> fp16
    prenorm_kernel<<<NBL,128>>>(x, mask, pu);
    // 3) W_out transpose
    wconv_kernel<<<dim3((DM+31)/32,    DIN/32), wb>>>(W_out, pwo, DIN, DM);
    // 4) in-projection (PROFILED SLOT)
    mma_gemm<3><<<dim3((DPROJ+127)/128, NBL/128), 256, GSMEM_BYTES>>>(
        pu, pwi, DPROJ, DM, nullptr, nullptr, nullptr, nullptr,
        out_z, pxraw, out_dt, dt_bias);
    // 5) W1 transpose
    wconv_kernel<<<dim3((DFF+31)/32,   DM/32),  wb>>>(W1,    pw1, DM,  DFF);
    // 6) W2 transpose
    wconv_kernel<<<dim3((DM+31)/32,    DFF/32), wb>>>(W2,    pw2, DFF, DM);
    // 7) conv + silu + mask
    conv_kernel<<<(int)(((long)NBL*CONVD + 255)/256), 256>>>(conv_w, conv_b, mask);
    // 8) bidirectional scan
    scan_kernel<<<dim3(2,NH,BATCH), 128>>>(out_dt, A_log, Dv, pyf, pyb);
    // 9) gated rmsnorm -> fp16
    gatednorm_kernel<<<NBL,256>>>(out_z, norm_w, py2);
    // 10) out projection -> m
    mma_gemm<0><<<dim3(DM/128, NBL/128), 256, GSMEM_BYTES>>>(
        py2, pwo, DM, DIN, out_m, nullptr, nullptr, nullptr,
        nullptr, nullptr, nullptr, nullptr);
    // 11) h = rmsnorm(2m) -> fp16
    postnorm_kernel<<<NBL,128>>>(out_m, ph);
    // 12) FFN up: gelu -> fp16
    mma_gemm<1><<<dim3(DFF/128, NBL/128), 256, GSMEM_BYTES>>>(
        ph, pw1, DFF, DM, nullptr, b1, nullptr, pff,
        nullptr, nullptr, nullptr, nullptr);
    // 13) FFN down + residual
    mma_gemm<2><<<dim3(DM/128, NBL/128), 256, GSMEM_BYTES>>>(
        pff, pw2, DM, DFF, out_x, b2, out_m, nullptr,
        nullptr, nullptr, nullptr, nullptr);
}

// round 11
// speedup vs baseline: 1.8514x; 1.4031x over previous
#include <cuda_runtime.h>
#include <cuda_fp16.h>
#include <math.h>
#include <stdint.h>

#define BATCH 8
#define SEQ   2048
#define NBL   (BATCH*SEQ)          // 16384
#define DM    512
#define DIN   1024
#define NH    16
#define HD    64
#define DS    64
#define CONVD 1152
#define DPROJ 2192
#define DFF   2048
#define EPSR  1e-6f

// ===================== scratch (static device; no cudaMalloc) =====================
static __device__ float g_xraw[(size_t)NBL*CONVD];  // in-proj xBC (pre-conv)
static __device__ float g_xbc[(size_t)NBL*CONVD];   // conv+silu output
static __device__ float g_yf[(size_t)NBL*DIN];      // forward scan out (+D*x)
static __device__ float g_yb[(size_t)NBL*DIN];      // backward scan out
// fp16 activations
static __device__ __half g_u[(size_t)NBL*DM];
static __device__ __half g_y2[(size_t)NBL*DIN];
static __device__ __half g_h[(size_t)NBL*DM];
static __device__ __half g_ff[(size_t)NBL*DFF];
// fp16 transposed weights [N,K]
static __device__ __half g_wi[(size_t)DPROJ*DM];
static __device__ __half g_wo[(size_t)DM*DIN];
static __device__ __half g_w1[(size_t)DFF*DM];
static __device__ __half g_w2[(size_t)DM*DFF];

// ===================== helpers =====================
__device__ __forceinline__ uint32_t smem_to_u32(const void* smem_ptr) {
    uint32_t addr;
    asm("{ .reg .u64 tmp; cvta.to.shared.u64 tmp, %1; cvt.u32.u64 %0, tmp; }"
        : "=r"(addr) : "l"(smem_ptr));
    return addr;
}
__device__ __forceinline__ void cp_async16(uint32_t dst, const void* src, uint32_t bytes){
    asm volatile("cp.async.cg.shared.global [%0], [%1], 16, %2;"
                 :: "r"(dst), "l"(src), "r"(bytes));
}
#define CP_COMMIT() asm volatile("cp.async.commit_group;")
#define CP_WAIT1()  asm volatile("cp.async.wait_group 1;")
#define CP_WAIT0()  asm volatile("cp.async.wait_group 0;")

__device__ __forceinline__ void ldm_x4(uint32_t addr, uint32_t& r0, uint32_t& r1,
                                       uint32_t& r2, uint32_t& r3){
    asm volatile("ldmatrix.sync.aligned.m8n8.x4.shared.b16 {%0,%1,%2,%3}, [%4];"
                 : "=r"(r0), "=r"(r1), "=r"(r2), "=r"(r3) : "r"(addr));
}
__device__ __forceinline__ void mma16816(float* c, const uint32_t* a, const uint32_t* b){
    asm volatile(
        "mma.sync.aligned.m16n8k16.row.col.f32.f16.f16.f32 "
        "{%0,%1,%2,%3}, {%4,%5,%6,%7}, {%8,%9}, {%0,%1,%2,%3};"
        : "+f"(c[0]), "+f"(c[1]), "+f"(c[2]), "+f"(c[3])
        : "r"(a[0]), "r"(a[1]), "r"(a[2]), "r"(a[3]), "r"(b[0]), "r"(b[1]));
}

__device__ __forceinline__ float siluf(float x){ return x / (1.f + expf(-x)); }
__device__ __forceinline__ float geluf(float x){
    float x3 = x*x*x;
    return 0.5f*x*(1.f + tanhf(0.7978845608028654f*(x + 0.044715f*x3)));
}
__device__ __forceinline__ float softplusf(float x){
    return fmaxf(x, 0.f) + log1pf(expf(-fabsf(x)));
}

// ===================== weight transpose: W[K,N] fp32 -> T[N,K] fp16 ==============
__global__ void wconv_kernel(const float* __restrict__ W,
                             __half* __restrict__ T, int K, int N){
    __shared__ float tile[32][33];
    int n0 = blockIdx.x*32, k0 = blockIdx.y*32;
    int tx = threadIdx.x, ty = threadIdx.y;   // 32 x 8
    #pragma unroll
    for (int i=0;i<32;i+=8){
        int k = k0+ty+i, n = n0+tx;
        tile[ty+i][tx] = (n < N) ? W[(size_t)k*N + n] : 0.f;
    }
    __syncthreads();
    #pragma unroll
    for (int i=0;i<32;i+=8){
        int n = n0+ty+i, k = k0+tx;
        if (n < N) T[(size_t)n*K + k] = __float2half(tile[tx][ty+i]);
    }
}

// ===================== fp16 HMMA GEMM, BK=64 (unchanged from R8) =================
#define BK 64
#define LDSB 144
#define MAT_ELEMS (128*72)
#define STAGE_BYTES (2*MAT_ELEMS*2)
#define GSMEM_BYTES (3*STAGE_BYTES)

template<int MODE>
__global__ void __launch_bounds__(256,2)
mma_gemm(const __half* __restrict__ A, const __half* __restrict__ B,
         int N, int K,
         float* __restrict__ C, const float* __restrict__ bias,
         const float* __restrict__ res, __half* __restrict__ Oh,
         float* __restrict__ z_out, float* __restrict__ xraw,
         float* __restrict__ dt_out, const float* __restrict__ dtb)
{
    extern __shared__ __half smem[];
    const uint32_t sb = smem_to_u32(smem);
    const int tid = threadIdx.x;
    const int lane = tid & 31, wid = tid >> 5;
    const int row0 = blockIdx.y * 128;
    const int n0   = blockIdx.x * 128;
    const int wm0 = (wid & 3) * 32;
    const int wn0 = (wid >> 2) * 64;

    const uint32_t aoff = (uint32_t)((lane & 15) * LDSB + (lane >> 4) * 16);
    const uint32_t boff = (uint32_t)(((lane & 7) + ((lane & 16) >> 1)) * LDSB + (lane & 8) * 2);

    float acc[2][8][4];
    #pragma unroll
    for (int i=0;i<2;i++)
        #pragma unroll
        for (int j=0;j<8;j++)
            #pragma unroll
            for (int q=0;q<4;q++) acc[i][j][q]=0.f;

    const int nch = K / BK;

    auto issue = [&](int ch){
        const int k0 = ch * BK;
        uint32_t base = sb + (uint32_t)((ch % 3) * STAGE_BYTES);
        #pragma unroll
        for (int i=0;i<4;i++){
            int id = tid + i*256;
            int r = id >> 3, c8e = (id & 7) * 8;
            size_t g = (size_t)(row0 + r) * K + k0 + c8e;
            uint32_t so = (uint32_t)(r * LDSB + c8e * 2);
            cp_async16(base + so, A + g, 16);
        }
        #pragma unroll
        for (int i=0;i<4;i++){
            int id = tid + i*256;
            int r = id >> 3, c8e = (id & 7) * 8;
            int n = n0 + r;
            int valid = (n < N);
            size_t g = (size_t)(valid ? n : 0) * K + k0 + c8e;
            uint32_t so = (uint32_t)(r * LDSB + c8e * 2);
            cp_async16(base + (uint32_t)MAT_ELEMS*2 + so, B + g, valid ? 16u : 0u);
        }
        CP_COMMIT();
    };

    issue(0); if (nch > 1) issue(1);
    for (int ch = 0; ch < nch; ch++){
        if (ch + 1 < nch) CP_WAIT1(); else CP_WAIT0();
        __syncthreads();
        if (ch + 2 < nch) issue(ch + 2);

        const uint32_t base = sb + (uint32_t)((ch % 3) * STAGE_BYTES);
        const uint32_t bA = base;
        const uint32_t bB = base + (uint32_t)MAT_ELEMS*2;

        #pragma unroll
        for (int ks = 0; ks < BK; ks += 16){
            uint32_t a[2][4], b[8][2];
            #pragma unroll
            for (int mt = 0; mt < 2; mt++){
                uint32_t ao = (uint32_t)((wm0 + mt*16) * LDSB + ks*2) + aoff;
                ldm_x4(bA + ao, a[mt][0], a[mt][1], a[mt][2], a[mt][3]);
            }
            #pragma unroll
            for (int p = 0; p < 4; p++){
                uint32_t bo = (uint32_t)((wn0 + p*16) * LDSB + ks*2) + boff;
                ldm_x4(bB + bo, b[2*p][0], b[2*p][1], b[2*p+1][0], b[2*p+1][1]);
            }
            #pragma unroll
            for (int mt = 0; mt < 2; mt++)
                #pragma unroll
                for (int nt = 0; nt < 8; nt++)
                    mma16816(acc[mt][nt], a[mt], b[nt]);
        }
        __syncthreads();
    }

    const int rb = row0 + wm0 + (lane >> 2);
    const int cb = n0 + wn0 + (lane & 3) * 2;
    #pragma unroll
    for (int mt = 0; mt < 2; mt++){
        #pragma unroll
        for (int nt = 0; nt < 8; nt++){
            int c = cb + nt*8;
            if (c >= N) continue;
            #pragma unroll
            for (int half = 0; half < 2; half++){
                int r = rb + mt*16 + half*8;
                float v0 = acc[mt][nt][half*2+0];
                float v1 = acc[mt][nt][half*2+1];
                size_t o = (size_t)r*N + c;
                if (MODE == 0){
                    *(float2*)(C + o) = make_float2(v0, v1);
                } else if (MODE == 1){
                    v0 = geluf(v0 + bias[c]);
                    v1 = geluf(v1 + bias[c+1]);
                    __half2 hp; hp.x = __float2half(v0); hp.y = __float2half(v1);
                    *(__half2*)(Oh + o) = hp;
                } else if (MODE == 2){
                    float2 rv = *(const float2*)(res + o);
                    *(float2*)(C + o) = make_float2(v0 + bias[c]   + 2.f*rv.x,
                                                    v1 + bias[c+1] + 2.f*rv.y);
                } else {
                    if (c < DIN){
                        *(float2*)(z_out + (size_t)r*DIN + c) = make_float2(v0, v1);
                    } else if (c < DIN + CONVD){
                        *(float2*)(xraw + (size_t)r*CONVD + (c - DIN)) = make_float2(v0, v1);
                    } else {
                        int hh2 = c - (DIN + CONVD);
                        dt_out[(size_t)r*NH + hh2]     = softplusf(v0 + dtb[hh2]);
                        dt_out[(size_t)r*NH + hh2 + 1] = softplusf(v1 + dtb[hh2+1]);
                    }
                }
            }
        }
    }
}

// ===================== u = rmsnorm(x*mask) -> fp16 =====================
__global__ void __launch_bounds__(128) prenorm_kernel(const float* __restrict__ x,
                                                      const float* __restrict__ mask,
                                                      __half* __restrict__ u){
    int row = blockIdx.x; int t = threadIdx.x;
    float mk = mask[row];
    float4 a = ((const float4*)(x + (size_t)row*DM))[t];
    a.x*=mk; a.y*=mk; a.z*=mk; a.w*=mk;
    float ss = a.x*a.x + a.y*a.y + a.z*a.z + a.w*a.w;
    __shared__ float sh[4];
    #pragma unroll
    for (int o=16;o;o>>=1) ss += __shfl_xor_sync(0xffffffffu, ss, o);
    if ((t&31)==0) sh[t>>5] = ss;
    __syncthreads();
    float inv = rsqrtf((sh[0]+sh[1]+sh[2]+sh[3])*(1.f/DM) + EPSR);
    __half2 p0, p1;
    p0.x = __float2half(a.x*inv); p0.y = __float2half(a.y*inv);
    p1.x = __float2half(a.z*inv); p1.y = __float2half(a.w*inv);
    size_t o = (size_t)row*DM + t*4;
    *(__half2*)(u+o)   = p0;
    *(__half2*)(u+o+2) = p1;
}

// ===================== conv + silu + mask, float4 over channels ==================
__global__ void conv_kernel(const float* __restrict__ cw, const float* __restrict__ cb,
                            const float* __restrict__ mask){
    long idx = (long)blockIdx.x*blockDim.x + threadIdx.x;   // over NBL*CONVD/4
    if (idx >= (long)NBL*(CONVD/4)) return;
    int c4 = (int)(idx % (CONVD/4));
    long bl = idx / (CONVD/4);
    int l = (int)(bl % SEQ);
    int c = c4 * 4;
    // per-channel tap vectors
    float4 w0 = *(const float4*)(cw + (size_t)c*4);
    float4 w1 = *(const float4*)(cw + (size_t)(c+1)*4);
    float4 w2 = *(const float4*)(cw + (size_t)(c+2)*4);
    float4 w3 = *(const float4*)(cw + (size_t)(c+3)*4);
    float4 acc = *(const float4*)(cb + c);
    float4 xt[4];
    #pragma unroll
    for (int i=0;i<4;i++){
        int ls = l + i - 3;
        if (ls >= 0) xt[i] = *(const float4*)(g_xraw + (size_t)(bl + (i-3))*CONVD + c);
        else         xt[i] = make_float4(0.f,0.f,0.f,0.f);
    }
    acc.x += xt[0].x*w0.x + xt[1].x*w0.y + xt[2].x*w0.z + xt[3].x*w0.w;
    acc.y += xt[0].y*w1.x + xt[1].y*w1.y + xt[2].y*w1.z + xt[3].y*w1.w;
    acc.z += xt[0].z*w2.x + xt[1].z*w2.y + xt[2].z*w2.z + xt[3].z*w2.w;
    acc.w += xt[0].w*w3.x + xt[1].w*w3.y + xt[2].w*w3.z + xt[3].w*w3.w;
    float mk = mask[bl];
    float4 o4;
    o4.x = siluf(acc.x)*mk; o4.y = siluf(acc.y)*mk;
    o4.z = siluf(acc.z)*mk; o4.w = siluf(acc.w)*mk;
    *(float4*)(g_xbc + (size_t)bl*CONVD + c) = o4;
}

// ===================== bidirectional SSM scan (float4 LDS, no atomics) ===========
// grid (2, NH, BATCH), 128 threads. Thread pair (2p,2p+1) owns state row p;
// each handles 32 of 64 state cols as 8 float4 groups. Broadcast pairs -> no conflicts.
#define CT 32
__global__ void __launch_bounds__(128) scan_kernel(const float* __restrict__ dtb,
                                                   const float* __restrict__ A_log,
                                                   const float* __restrict__ Dv,
                                                   float* __restrict__ yf,
                                                   float* __restrict__ yb){
    const int dir = blockIdx.x;
    const int h   = blockIdx.y;
    const int b   = blockIdx.z;
    const int tid = threadIdx.x;
    const int p    = tid >> 1;
    const int half = tid & 1;
    const int nbase = half << 5;
    const float Ah = -expf(A_log[h]);
    const float Dh = Dv[h];
    float st[32];
    #pragma unroll
    for (int j=0;j<32;j++) st[j]=0.f;
    __shared__ float Bs[CT][64];
    __shared__ float Cs[CT][64];
    __shared__ float Xs[CT][64];
    __shared__ float Ts[CT];
    __shared__ float dAs[CT];
    const size_t base = (size_t)b*SEQ;
    float* yout = dir ? yb : yf;
    for (int t0=0; t0<SEQ; t0+=CT){
        // fill smem with float4 loads: CT*16 float4s per array
        for (int idx = tid; idx < CT*16; idx += 128){
            int tt = idx >> 4, q = idx & 15;
            int t = dir ? (SEQ-1-(t0+tt)) : (t0+tt);
            const float4* src = (const float4*)(g_xbc + (base + t)*(size_t)CONVD);
            ((float4*)&Bs[tt][0])[q] = src[(DIN>>2) + q];
            ((float4*)&Cs[tt][0])[q] = src[((DIN+DS)>>2) + q];
            ((float4*)&Xs[tt][0])[q] = src[((h*HD)>>2) + q];
        }
        if (tid < CT){
            int t = dir ? (SEQ-1-(t0+tid)) : (t0+tid);
            float dtv = dtb[(base + t)*NH + h];
            Ts[tid] = dtv;
            dAs[tid] = __expf(dtv*Ah);
        }
        __syncthreads();
        for (int tt=0; tt<CT; tt++){
            float dtv = Ts[tt];
            float dA  = dAs[tt];
            float xv  = Xs[tt][p];
            float dtx = dtv * xv;
            const float4* Bp = (const float4*)(&Bs[tt][nbase]);
            const float4* Cp = (const float4*)(&Cs[tt][nbase]);
            float y0=0.f, y1=0.f, y2v=0.f, y3=0.f;
            #pragma unroll
            for (int j=0;j<8;j++){
                float4 bv = Bp[j];
                float4 cv = Cp[j];
                st[4*j+0] = fmaf(dA, st[4*j+0], dtx*bv.x); y0  = fmaf(st[4*j+0], cv.x, y0);
                st[4*j+1] = fmaf(dA, st[4*j+1], dtx*bv.y); y1  = fmaf(st[4*j+1], cv.y, y1);
                st[4*j+2] = fmaf(dA, st[4*j+2], dtx*bv.z); y2v = fmaf(st[4*j+2], cv.z, y2v);
                st[4*j+3] = fmaf(dA, st[4*j+3], dtx*bv.w); y3  = fmaf(st[4*j+3], cv.w, y3);
            }
            float y = (y0+y1) + (y2v+y3);
            y += __shfl_xor_sync(0xffffffffu, y, 1);
            if (half == 0){
                int t = dir ? (SEQ-1-(t0+tt)) : (t0+tt);
                float yv = y;
                if (dir==0) yv = fmaf(Dh, xv, yv);
                yout[(base + t)*(size_t)DIN + h*HD + p] = yv;
            }
        }
        __syncthreads();
    }
}

// ===================== y2 = rmsnorm((yf+yb) * silu(z)) * norm_w -> fp16 ==========
__global__ void __launch_bounds__(256) gatednorm_kernel(const float* __restrict__ z,
                                                        const float* __restrict__ w,
                                                        __half* __restrict__ y2){
    int row = blockIdx.x; int t = threadIdx.x;
    float4 ya = ((const float4*)(g_yf + (size_t)row*DIN))[t];
    float4 ybv = ((const float4*)(g_yb + (size_t)row*DIN))[t];
    float4 zv = ((const float4*)(z    + (size_t)row*DIN))[t];
    float4 v;
    v.x = (ya.x + ybv.x) * siluf(zv.x);
    v.y = (ya.y + ybv.y) * siluf(zv.y);
    v.z = (ya.z + ybv.z) * siluf(zv.z);
    v.w = (ya.w + ybv.w) * siluf(zv.w);
    float ss = v.x*v.x + v.y*v.y + v.z*v.z + v.w*v.w;
    __shared__ float sh[8];
    #pragma unroll
    for (int o=16;o;o>>=1) ss += __shfl_xor_sync(0xffffffffu, ss, o);
    if ((t&31)==0) sh[t>>5] = ss;
    __syncthreads();
    float tot = sh[0]+sh[1]+sh[2]+sh[3]+sh[4]+sh[5]+sh[6]+sh[7];
    float inv = rsqrtf(tot*(1.f/DIN) + EPSR);
    float4 wv = ((const float4*)w)[t];
    __half2 p0, p1;
    p0.x = __float2half(v.x*inv*wv.x); p0.y = __float2half(v.y*inv*wv.y);
    p1.x = __float2half(v.z*inv*wv.z); p1.y = __float2half(v.w*inv*wv.w);
    size_t o = (size_t)row*DIN + t*4;
    *(__half2*)(y2+o)   = p0;
    *(__half2*)(y2+o+2) = p1;
}

// ===================== h = rmsnorm(2*m) -> fp16 =====================
__global__ void __launch_bounds__(128) postnorm_kernel(const float* __restrict__ m,
                                                       __half* __restrict__ hbuf){
    int row = blockIdx.x; int t = threadIdx.x;
    float4 mv = ((const float4*)(m + (size_t)row*DM))[t];
    float4 v = make_float4(2.f*mv.x, 2.f*mv.y, 2.f*mv.z, 2.f*mv.w);
    float ss = v.x*v.x + v.y*v.y + v.z*v.z + v.w*v.w;
    __shared__ float sh[4];
    #pragma unroll
    for (int o=16;o;o>>=1) ss += __shfl_xor_sync(0xffffffffu, ss, o);
    if ((t&31)==0) sh[t>>5] = ss;
    __syncthreads();
    float inv = rsqrtf((sh[0]+sh[1]+sh[2]+sh[3])*(1.f/DM) + EPSR);
    __half2 p0, p1;
    p0.x = __float2half(v.x*inv); p0.y = __float2half(v.y*inv);
    p1.x = __float2half(v.z*inv); p1.y = __float2half(v.w*inv);
    size_t o = (size_t)row*DM + t*4;
    *(__half2*)(hbuf+o)   = p0;
    *(__half2*)(hbuf+o+2) = p1;
}

extern "C" void kernel_launch(void* const* d_in, const int* in_sizes, int n_in,
                              void* d_out, int out_size){
    const float* x      = (const float*)d_in[0];
    const float* mask   = (const float*)d_in[1];
    const float* W_in   = (const float*)d_in[2];
    const float* conv_w = (const float*)d_in[3];
    const float* conv_b = (const float*)d_in[4];
    const float* dt_bias= (const float*)d_in[5];
    const float* A_log  = (const float*)d_in[6];
    const float* Dv     = (const float*)d_in[7];
    const float* norm_w = (const float*)d_in[8];
    const float* W_out  = (const float*)d_in[9];
    const float* W1     = (const float*)d_in[10];
    const float* b1     = (const float*)d_in[11];
    const float* W2     = (const float*)d_in[12];
    const float* b2     = (const float*)d_in[13];

    float* out_x  = (float*)d_out;
    float* out_m  = out_x  + (size_t)NBL*DM;
    float* out_dt = out_m  + (size_t)NBL*DM;
    float* out_z  = out_dt + (size_t)NBL*NH;

    float *pxraw, *pyf, *pyb;
    __half *pu, *py2, *ph, *pff, *pwi, *pwo, *pw1, *pw2;
    cudaGetSymbolAddress((void**)&pxraw, g_xraw);
    cudaGetSymbolAddress((void**)&pyf, g_yf); cudaGetSymbolAddress((void**)&pyb, g_yb);
    cudaGetSymbolAddress((void**)&pu,  g_u);  cudaGetSymbolAddress((void**)&py2, g_y2);
    cudaGetSymbolAddress((void**)&ph,  g_h);  cudaGetSymbolAddress((void**)&pff, g_ff);
    cudaGetSymbolAddress((void**)&pwi, g_wi); cudaGetSymbolAddress((void**)&pwo, g_wo);
    cudaGetSymbolAddress((void**)&pw1, g_w1); cudaGetSymbolAddress((void**)&pw2, g_w2);

    cudaFuncSetAttribute(mma_gemm<0>, cudaFuncAttributeMaxDynamicSharedMemorySize, GSMEM_BYTES);
    cudaFuncSetAttribute(mma_gemm<1>, cudaFuncAttributeMaxDynamicSharedMemorySize, GSMEM_BYTES);
    cudaFuncSetAttribute(mma_gemm<2>, cudaFuncAttributeMaxDynamicSharedMemorySize, GSMEM_BYTES);
    cudaFuncSetAttribute(mma_gemm<3>, cudaFuncAttributeMaxDynamicSharedMemorySize, GSMEM_BYTES);

    dim3 wb(32,8);
    // slot 4 (profiled) = conv_kernel this round
    // 1) W_in transpose
    wconv_kernel<<<dim3((DPROJ+31)/32, DM/32),  wb>>>(W_in,  pwi, DM,  DPROJ);
    // 2) pre-norm -> fp16
    prenorm_kernel<<<NBL,128>>>(x, mask, pu);
    // 3) in-projection (fused: z, xBC, dt)
    mma_gemm<3><<<dim3((DPROJ+127)/128, NBL/128), 256, GSMEM_BYTES>>>(
        pu, pwi, DPROJ, DM, nullptr, nullptr, nullptr, nullptr,
        out_z, pxraw, out_dt, dt_bias);
    // 4) conv + silu + mask (PROFILED SLOT)
    conv_kernel<<<(int)(((long)NBL*(CONVD/4) + 255)/256), 256>>>(conv_w, conv_b, mask);
    // 5) bidirectional scan
    scan_kernel<<<dim3(2,NH,BATCH), 128>>>(out_dt, A_log, Dv, pyf, pyb);
    // 6) W_out transpose
    wconv_kernel<<<dim3((DM+31)/32,    DIN/32), wb>>>(W_out, pwo, DIN, DM);
    // 7) gated rmsnorm -> fp16
    gatednorm_kernel<<<NBL,256>>>(out_z, norm_w, py2);
    // 8) out projection -> m
    mma_gemm<0><<<dim3(DM/128, NBL/128), 256, GSMEM_BYTES>>>(
        py2, pwo, DM, DIN, out_m, nullptr, nullptr, nullptr,
        nullptr, nullptr, nullptr, nullptr);
    // 9) h = rmsnorm(2m) -> fp16
    postnorm_kernel<<<NBL,128>>>(out_m, ph);
    // 10) W1 transpose
    wconv_kernel<<<dim3((DFF+31)/32,   DM/32),  wb>>>(W1,    pw1, DM,  DFF);
    // 11) FFN up: gelu -> fp16
    mma_gemm<1><<<dim3(DFF/128, NBL/128), 256, GSMEM_BYTES>>>(
        ph, pw1, DFF, DM, nullptr, b1, nullptr, pff,
        nullptr, nullptr, nullptr, nullptr);
    // 12) W2 transpose
    wconv_kernel<<<dim3((DM+31)/32,    DFF/32), wb>>>(W2,    pw2, DFF, DM);
    // 13) FFN down + residual
    mma_gemm<2><<<dim3(DM/128, NBL/128), 256, GSMEM_BYTES>>>(
        pff, pw2, DM, DFF, out_x, b2, out_m, nullptr,
        nullptr, nullptr, nullptr, nullptr);
}